// round 1
// baseline (speedup 1.0000x reference)
#include <cuda_runtime.h>

#define NB 4
#define NL 4096
#define NH 16
#define ND 1024
#define Nd 64

// Scratch (device globals -- no allocation allowed)
__device__ float g_qkv[(size_t)NB * NL * 3 * ND];   // (B,L,3D) = 201 MB
__device__ float g_y[(size_t)NB * NL * ND];         // (B,L,D)  = 67 MB

// ---------------------------------------------------------------------------
// C[m,n] = sum_k A[m,k] * Bw[n,k] + bias[n]
// A: (M,K) row-major, Bw: (N,K) row-major. M,N multiples of 128, K multiple of 8.
// ---------------------------------------------------------------------------
__global__ __launch_bounds__(256) void gemm_nt_bias(
    const float* __restrict__ A, const float* __restrict__ Bw,
    const float* __restrict__ bias, float* __restrict__ C,
    int M, int N, int K)
{
    __shared__ float As[8][128];
    __shared__ float Bs[8][128];

    const int tid = threadIdx.x;
    const int bm = blockIdx.y * 128;
    const int bn = blockIdx.x * 128;
    const int tx = tid & 15;         // 16 col groups
    const int ty = tid >> 4;         // 16 row groups

    const int lrow = tid >> 1;       // 0..127
    const int lc4  = (tid & 1) * 4;  // 0 or 4

    const float* Ap = A + (size_t)(bm + lrow) * K + lc4;
    const float* Bp = Bw + (size_t)(bn + lrow) * K + lc4;

    float acc[8][8];
    #pragma unroll
    for (int i = 0; i < 8; i++)
        #pragma unroll
        for (int j = 0; j < 8; j++)
            acc[i][j] = 0.0f;

    for (int k0 = 0; k0 < K; k0 += 8) {
        float4 av = *(const float4*)(Ap + k0);
        float4 bv = *(const float4*)(Bp + k0);
        As[lc4 + 0][lrow] = av.x;
        As[lc4 + 1][lrow] = av.y;
        As[lc4 + 2][lrow] = av.z;
        As[lc4 + 3][lrow] = av.w;
        Bs[lc4 + 0][lrow] = bv.x;
        Bs[lc4 + 1][lrow] = bv.y;
        Bs[lc4 + 2][lrow] = bv.z;
        Bs[lc4 + 3][lrow] = bv.w;
        __syncthreads();

        #pragma unroll
        for (int kk = 0; kk < 8; kk++) {
            float a[8], b[8];
            *(float4*)(a)     = *(const float4*)(&As[kk][ty * 8]);
            *(float4*)(a + 4) = *(const float4*)(&As[kk][ty * 8 + 4]);
            *(float4*)(b)     = *(const float4*)(&Bs[kk][tx * 8]);
            *(float4*)(b + 4) = *(const float4*)(&Bs[kk][tx * 8 + 4]);
            #pragma unroll
            for (int i = 0; i < 8; i++)
                #pragma unroll
                for (int j = 0; j < 8; j++)
                    acc[i][j] = fmaf(a[i], b[j], acc[i][j]);
        }
        __syncthreads();
    }

    // epilogue with bias
    float bb[8];
    *(float4*)(bb)     = *(const float4*)(bias + bn + tx * 8);
    *(float4*)(bb + 4) = *(const float4*)(bias + bn + tx * 8 + 4);

    #pragma unroll
    for (int i = 0; i < 8; i++) {
        const int row = bm + ty * 8 + i;
        float* Cp = C + (size_t)row * N + bn + tx * 8;
        float4 o0, o1;
        o0.x = acc[i][0] + bb[0];
        o0.y = acc[i][1] + bb[1];
        o0.z = acc[i][2] + bb[2];
        o0.w = acc[i][3] + bb[3];
        o1.x = acc[i][4] + bb[4];
        o1.y = acc[i][5] + bb[5];
        o1.z = acc[i][6] + bb[6];
        o1.w = acc[i][7] + bb[7];
        *(float4*)(Cp)     = o0;
        *(float4*)(Cp + 4) = o1;
    }
}

// ---------------------------------------------------------------------------
// Sequential STP scan.
//   u = W_static + state ; u <- r*u + (g*v*k + c),  c = sigmoid(Lambda)*W,
//   r = 1 - sigmoid(Lambda), g = Gamma/sqrt(d) (k-scale folded in).
//   y_t[i] = sum_j u[i,j] * q_t[j]
// grid (4, B*H), block 128.  Warp = 4 rows x 64 cols; lane = (row_grp[2b], col_grp[3b]).
// Each lane: 8 contiguous cols of one row (u,r,g,c in registers).
// ---------------------------------------------------------------------------
__global__ __launch_bounds__(128) void stp_scan(
    const float* __restrict__ Wst,
    const float* __restrict__ Lam,
    const float* __restrict__ Gam)
{
    const int bh = blockIdx.y;
    const int b = bh >> 4;
    const int h = bh & 15;
    const int tid = threadIdx.x;
    const int w = tid >> 5;
    const int lane = tid & 31;
    const int rg = lane >> 3;      // 0..3
    const int cg = lane & 7;       // 0..7
    const int i  = (blockIdx.x << 4) + (w << 2) + rg;  // row 0..63
    const int j0 = cg << 3;                            // col base

    float u[8], r[8], g[8], cw[8];
    {
        const int pbase = (h * Nd + i) * Nd + j0;
        float4 wa = *(const float4*)(Wst + pbase);
        float4 wb = *(const float4*)(Wst + pbase + 4);
        float4 la = *(const float4*)(Lam + pbase);
        float4 lb = *(const float4*)(Lam + pbase + 4);
        float4 ga = *(const float4*)(Gam + pbase);
        float4 gb = *(const float4*)(Gam + pbase + 4);
        float wv[8] = {wa.x, wa.y, wa.z, wa.w, wb.x, wb.y, wb.z, wb.w};
        float lv[8] = {la.x, la.y, la.z, la.w, lb.x, lb.y, lb.z, lb.w};
        float gv[8] = {ga.x, ga.y, ga.z, ga.w, gb.x, gb.y, gb.z, gb.w};
        #pragma unroll
        for (int jj = 0; jj < 8; jj++) {
            float sg = 1.0f / (1.0f + __expf(-lv[jj]));  // sigmoid(Lambda)
            r[jj]  = 1.0f - sg;          // retention
            cw[jj] = sg * wv[jj];        // (1-retention)*W
            u[jj]  = wv[jj];             // W + state0
            g[jj]  = gv[jj] * 0.125f;    // Gamma * (1/sqrt(64)) folded k-scale
        }
    }

    const float* base = g_qkv + (size_t)b * NL * 3 * ND + h * Nd;
    float* yout = g_y + (size_t)b * NL * ND + h * Nd + i;

    // prefetch t = 0
    float4 qa, qb, ka, kb;
    float v;
    {
        const float* p = base;
        qa = *(const float4*)(p + j0);
        qb = *(const float4*)(p + j0 + 4);
        ka = *(const float4*)(p + ND + j0);
        kb = *(const float4*)(p + ND + j0 + 4);
        v  = p[2 * ND + i];
    }

    for (int t = 0; t < NL; ++t) {
        const float4 cqa = qa, cqb = qb, cka = ka, ckb = kb;
        const float cv = v;

        // prefetch next step (clamped; last iteration reloads same data harmlessly)
        {
            int tn = t + 1;
            if (tn > NL - 1) tn = NL - 1;
            const float* pn = base + (size_t)tn * (3 * ND);
            qa = *(const float4*)(pn + j0);
            qb = *(const float4*)(pn + j0 + 4);
            ka = *(const float4*)(pn + ND + j0);
            kb = *(const float4*)(pn + ND + j0 + 4);
            v  = pn[2 * ND + i];
        }

        const float kv[8] = {cka.x, cka.y, cka.z, cka.w, ckb.x, ckb.y, ckb.z, ckb.w};
        const float qv[8] = {cqa.x, cqa.y, cqa.z, cqa.w, cqb.x, cqb.y, cqb.z, cqb.w};

        float yp = 0.0f;
        #pragma unroll
        for (int jj = 0; jj < 8; jj++) {
            float vk  = cv * kv[jj];
            float tmp = fmaf(g[jj], vk, cw[jj]);
            u[jj] = fmaf(r[jj], u[jj], tmp);
            yp = fmaf(u[jj], qv[jj], yp);
        }

        // reduce over the 8 col-group lanes (low 3 bits of lane id)
        yp += __shfl_xor_sync(0xffffffffu, yp, 1);
        yp += __shfl_xor_sync(0xffffffffu, yp, 2);
        yp += __shfl_xor_sync(0xffffffffu, yp, 4);
        if (cg == 0) yout[(size_t)t * ND] = yp;
    }
}

// ---------------------------------------------------------------------------

extern "C" void kernel_launch(void* const* d_in, const int* in_sizes, int n_in,
                              void* d_out, int out_size)
{
    const float* x          = (const float*)d_in[0];
    const float* Wqkv_w     = (const float*)d_in[1];
    const float* Wqkv_b     = (const float*)d_in[2];
    const float* out_w      = (const float*)d_in[3];
    const float* out_b      = (const float*)d_in[4];
    const float* W_static   = (const float*)d_in[5];
    const float* Lambda_raw = (const float*)d_in[6];
    const float* Gamma      = (const float*)d_in[7];

    float* qkv = nullptr;
    float* y   = nullptr;
    cudaGetSymbolAddress((void**)&qkv, g_qkv);
    cudaGetSymbolAddress((void**)&y,   g_y);

    const int M = NB * NL;  // 16384

    // qkv = x @ Wqkv_w^T + Wqkv_b    (M x 3072, K=1024)
    gemm_nt_bias<<<dim3((3 * ND) / 128, M / 128), 256>>>(
        x, Wqkv_w, Wqkv_b, qkv, M, 3 * ND, ND);

    // sequential STP scan -> y (B,L,D)
    stp_scan<<<dim3(4, NB * NH), 128>>>(W_static, Lambda_raw, Gamma);

    // out = y @ out_w^T + out_b      (M x 1024, K=1024)
    gemm_nt_bias<<<dim3(ND / 128, M / 128), 256>>>(
        y, out_w, out_b, (float*)d_out, M, ND, ND);
}

// round 3
// speedup vs baseline: 1.3517x; 1.3517x over previous
#include <cuda_runtime.h>
#include <cuda_bf16.h>
#include <cstdint>

#define NB 4
#define NL 4096
#define NH 16
#define ND 1024
#define Nd 64
#define MTOT (NB * NL)          // 16384
#define K3 3072                 // 3 * 1024 (split-bf16 extended K)

// ---------------------------------------------------------------------------
// Device-global scratch (no allocations allowed)
// ---------------------------------------------------------------------------
__device__ float g_qkv[(size_t)NB * NL * 3 * ND];           // (B,L,3D) f32
__device__ float g_y[(size_t)NB * NL * ND];                 // (B,L,D)  f32
__device__ __nv_bfloat16 g_sA[(size_t)MTOT * K3];           // split A (x, then y)
__device__ __nv_bfloat16 g_sB1[(size_t)3 * ND * K3];        // split Wqkv_w
__device__ __nv_bfloat16 g_sB2[(size_t)ND * K3];            // split out_w

// ---------------------------------------------------------------------------
__device__ __forceinline__ uint32_t smem_u32(const void* p) {
    uint32_t a;
    asm("{ .reg .u64 t; cvta.to.shared.u64 t, %1; cvt.u32.u64 %0, t; }"
        : "=r"(a) : "l"(p));
    return a;
}

__device__ __forceinline__ void ldsm_x4(uint32_t* r, uint32_t addr) {
    asm volatile("ldmatrix.sync.aligned.m8n8.x4.shared.b16 {%0,%1,%2,%3}, [%4];"
                 : "=r"(r[0]), "=r"(r[1]), "=r"(r[2]), "=r"(r[3]) : "r"(addr));
}

__device__ __forceinline__ void mma_bf16(float* d, const uint32_t* a, const uint32_t* b) {
    asm volatile(
        "mma.sync.aligned.m16n8k16.row.col.f32.bf16.bf16.f32 "
        "{%0,%1,%2,%3}, {%4,%5,%6,%7}, {%8,%9}, {%0,%1,%2,%3};"
        : "+f"(d[0]), "+f"(d[1]), "+f"(d[2]), "+f"(d[3])
        : "r"(a[0]), "r"(a[1]), "r"(a[2]), "r"(a[3]), "r"(b[0]), "r"(b[1]));
}

__device__ __forceinline__ void cp16(uint32_t saddr, const void* gaddr) {
    asm volatile("cp.async.cg.shared.global [%0], [%1], 16;" :: "r"(saddr), "l"(gaddr));
}

// ---------------------------------------------------------------------------
// Split-bf16 conversion: src (R,K) f32 -> dst (R,3K) bf16.
//   A-side (bside=0): [hi | lo | hi];  B-side (bside=1): [hi | hi | lo]
// ---------------------------------------------------------------------------
__global__ __launch_bounds__(256) void split3_kernel(
    const float* __restrict__ src, __nv_bfloat16* __restrict__ dst,
    int K, long total, int bside)
{
    long i = ((long)blockIdx.x * blockDim.x + threadIdx.x) * 4;
    if (i >= total) return;
    float4 v = *(const float4*)(src + i);
    int r = (int)(i / K);
    int k = (int)(i - (long)r * K);
    float vv[4] = {v.x, v.y, v.z, v.w};
    __nv_bfloat16 hi[4], lo[4];
    #pragma unroll
    for (int j = 0; j < 4; j++) {
        hi[j] = __float2bfloat16(vv[j]);
        lo[j] = __float2bfloat16(vv[j] - __bfloat162float(hi[j]));
    }
    __nv_bfloat162 h01, h23, l01, l23;
    h01.x = hi[0]; h01.y = hi[1]; h23.x = hi[2]; h23.y = hi[3];
    l01.x = lo[0]; l01.y = lo[1]; l23.x = lo[2]; l23.y = lo[3];

    __nv_bfloat16* d0 = dst + (size_t)r * (3 * K) + k;
    *(__nv_bfloat162*)(d0)     = h01;
    *(__nv_bfloat162*)(d0 + 2) = h23;
    if (bside == 0) {
        *(__nv_bfloat162*)(d0 + K)         = l01;
        *(__nv_bfloat162*)(d0 + K + 2)     = l23;
        *(__nv_bfloat162*)(d0 + 2 * K)     = h01;
        *(__nv_bfloat162*)(d0 + 2 * K + 2) = h23;
    } else {
        *(__nv_bfloat162*)(d0 + K)         = h01;
        *(__nv_bfloat162*)(d0 + K + 2)     = h23;
        *(__nv_bfloat162*)(d0 + 2 * K)     = l01;
        *(__nv_bfloat162*)(d0 + 2 * K + 2) = l23;
    }
}

// ---------------------------------------------------------------------------
// mma.sync bf16 GEMM: C[m,n] = sum_k A[m,k]*Bw[n,k] + bias[n]
// A (M,K) bf16 row-major, Bw (N,K) bf16 row-major.
// 128x128 CTA tile, BK=32, 8 warps (4m x 2n), warp tile 32x64.
// cp.async double-buffered smem; stride-40 rows (conflict-free ldmatrix).
// ---------------------------------------------------------------------------
#define SMSTRIDE 40   // bf16 elements per smem row (80 bytes)

__global__ __launch_bounds__(256, 1) void gemm_mma(
    const __nv_bfloat16* __restrict__ A, const __nv_bfloat16* __restrict__ Bw,
    const float* __restrict__ bias, float* __restrict__ C,
    int N, int K)
{
    __shared__ __align__(16) __nv_bfloat16 smA[2][128 * SMSTRIDE];
    __shared__ __align__(16) __nv_bfloat16 smB[2][128 * SMSTRIDE];

    const int tid = threadIdx.x;
    const int wid = tid >> 5;
    const int lane = tid & 31;
    const int wm = wid & 3;          // 0..3
    const int wn = wid >> 2;         // 0..1
    const int bm = blockIdx.y * 128;
    const int bn = blockIdx.x * 128;

    // cp.async: each thread loads 2 x 16B for A and 2 x 16B for B per chunk
    const int r0 = tid >> 2;         // 0..63
    const int sg = tid & 3;          // 16B segment within the 64B k-chunk
    const __nv_bfloat16* Ag = A + (size_t)(bm + r0) * K + sg * 8;
    const __nv_bfloat16* Bg = Bw + (size_t)(bn + r0) * K + sg * 8;
    const uint32_t sAd = smem_u32(&smA[0][0]) + (uint32_t)(r0 * 80 + sg * 16);
    const uint32_t sBd = smem_u32(&smB[0][0]) + (uint32_t)(r0 * 80 + sg * 16);
    const size_t rowK64 = (size_t)64 * K;

    // ldmatrix base addresses
    const int l15 = lane & 15;
    const uint32_t aBase = smem_u32(&smA[0][0])
        + (uint32_t)((wm * 32 + l15) * 80 + (lane >> 4) * 16);
    const int bnl = (lane & 7) + ((lane >> 4) & 1) * 8;
    const uint32_t bBase = smem_u32(&smB[0][0])
        + (uint32_t)((wn * 64 + bnl) * 80 + ((lane >> 3) & 1) * 16);

    float acc[2][8][4];
    #pragma unroll
    for (int mf = 0; mf < 2; mf++)
        #pragma unroll
        for (int nf = 0; nf < 8; nf++)
            #pragma unroll
            for (int j = 0; j < 4; j++)
                acc[mf][nf][j] = 0.0f;

    const int nch = K / 32;          // 96
    const uint32_t STAGE = 128 * 80; // bytes per stage

    // prologue: load chunk 0 into stage 0
    {
        cp16(sAd, Ag);
        cp16(sAd + 64 * 80, Ag + rowK64);
        cp16(sBd, Bg);
        cp16(sBd + 64 * 80, Bg + rowK64);
        asm volatile("cp.async.commit_group;" ::: "memory");
    }

    #pragma unroll 1
    for (int c = 0; c < nch; ++c) {
        if (c + 1 < nch) {
            const uint32_t so = ((c + 1) & 1) * STAGE;
            const __nv_bfloat16* Agn = Ag + (size_t)(c + 1) * 32;
            const __nv_bfloat16* Bgn = Bg + (size_t)(c + 1) * 32;
            cp16(sAd + so, Agn);
            cp16(sAd + so + 64 * 80, Agn + rowK64);
            cp16(sBd + so, Bgn);
            cp16(sBd + so + 64 * 80, Bgn + rowK64);
        }
        asm volatile("cp.async.commit_group;" ::: "memory");
        asm volatile("cp.async.wait_group 1;" ::: "memory");
        __syncthreads();

        const uint32_t so = (c & 1) * STAGE;
        const uint32_t aA = aBase + so;
        const uint32_t bA = bBase + so;

        #pragma unroll
        for (int ks = 0; ks < 2; ++ks) {
            uint32_t afr[2][4];
            ldsm_x4(afr[0], aA + ks * 32);
            ldsm_x4(afr[1], aA + 16 * 80 + ks * 32);
            uint32_t bfr[4][4];
            #pragma unroll
            for (int nq = 0; nq < 4; ++nq)
                ldsm_x4(bfr[nq], bA + nq * 16 * 80 + ks * 32);

            #pragma unroll
            for (int mf = 0; mf < 2; ++mf)
                #pragma unroll
                for (int nf = 0; nf < 8; ++nf)
                    mma_bf16(acc[mf][nf], afr[mf], &bfr[nf >> 1][(nf & 1) * 2]);
        }
        __syncthreads();
    }

    // epilogue with bias
    const int erow = lane >> 2;
    const int ecol = (lane & 3) * 2;
    #pragma unroll
    for (int mf = 0; mf < 2; ++mf) {
        const int row = bm + wm * 32 + mf * 16 + erow;
        #pragma unroll
        for (int nf = 0; nf < 8; ++nf) {
            const int col = bn + wn * 64 + nf * 8 + ecol;
            float2 bb = *(const float2*)(bias + col);
            float2 o0, o1;
            o0.x = acc[mf][nf][0] + bb.x;
            o0.y = acc[mf][nf][1] + bb.y;
            o1.x = acc[mf][nf][2] + bb.x;
            o1.y = acc[mf][nf][3] + bb.y;
            *(float2*)(C + (size_t)row * N + col) = o0;
            *(float2*)(C + (size_t)(row + 8) * N + col) = o1;
        }
    }
}

// ---------------------------------------------------------------------------
// Sequential STP scan (unchanged).
// ---------------------------------------------------------------------------
__global__ __launch_bounds__(128) void stp_scan(
    const float* __restrict__ Wst,
    const float* __restrict__ Lam,
    const float* __restrict__ Gam)
{
    const int bh = blockIdx.y;
    const int b = bh >> 4;
    const int h = bh & 15;
    const int tid = threadIdx.x;
    const int w = tid >> 5;
    const int lane = tid & 31;
    const int rg = lane >> 3;
    const int cg = lane & 7;
    const int i = (blockIdx.x << 4) + (w << 2) + rg;
    const int j0 = cg << 3;

    float u[8], r[8], g[8], cw[8];
    {
        const int pbase = (h * Nd + i) * Nd + j0;
        float4 wa = *(const float4*)(Wst + pbase);
        float4 wb = *(const float4*)(Wst + pbase + 4);
        float4 la = *(const float4*)(Lam + pbase);
        float4 lb = *(const float4*)(Lam + pbase + 4);
        float4 ga = *(const float4*)(Gam + pbase);
        float4 gb = *(const float4*)(Gam + pbase + 4);
        float wv[8] = {wa.x, wa.y, wa.z, wa.w, wb.x, wb.y, wb.z, wb.w};
        float lv[8] = {la.x, la.y, la.z, la.w, lb.x, lb.y, lb.z, lb.w};
        float gv[8] = {ga.x, ga.y, ga.z, ga.w, gb.x, gb.y, gb.z, gb.w};
        #pragma unroll
        for (int jj = 0; jj < 8; jj++) {
            float sg = 1.0f / (1.0f + __expf(-lv[jj]));
            r[jj] = 1.0f - sg;
            cw[jj] = sg * wv[jj];
            u[jj] = wv[jj];
            g[jj] = gv[jj] * 0.125f;
        }
    }

    const float* base = g_qkv + (size_t)b * NL * 3 * ND + h * Nd;
    float* yout = g_y + (size_t)b * NL * ND + h * Nd + i;

    float4 qa, qb, ka, kb;
    float v;
    {
        const float* p = base;
        qa = *(const float4*)(p + j0);
        qb = *(const float4*)(p + j0 + 4);
        ka = *(const float4*)(p + ND + j0);
        kb = *(const float4*)(p + ND + j0 + 4);
        v = p[2 * ND + i];
    }

    for (int t = 0; t < NL; ++t) {
        const float4 cqa = qa, cqb = qb, cka = ka, ckb = kb;
        const float cv = v;
        {
            int tn = t + 1;
            if (tn > NL - 1) tn = NL - 1;
            const float* pn = base + (size_t)tn * (3 * ND);
            qa = *(const float4*)(pn + j0);
            qb = *(const float4*)(pn + j0 + 4);
            ka = *(const float4*)(pn + ND + j0);
            kb = *(const float4*)(pn + ND + j0 + 4);
            v = pn[2 * ND + i];
        }

        const float kv[8] = {cka.x, cka.y, cka.z, cka.w, ckb.x, ckb.y, ckb.z, ckb.w};
        const float qv[8] = {cqa.x, cqa.y, cqa.z, cqa.w, cqb.x, cqb.y, cqb.z, cqb.w};

        float yp = 0.0f;
        #pragma unroll
        for (int jj = 0; jj < 8; jj++) {
            float vk = cv * kv[jj];
            float tmp = fmaf(g[jj], vk, cw[jj]);
            u[jj] = fmaf(r[jj], u[jj], tmp);
            yp = fmaf(u[jj], qv[jj], yp);
        }

        yp += __shfl_xor_sync(0xffffffffu, yp, 1);
        yp += __shfl_xor_sync(0xffffffffu, yp, 2);
        yp += __shfl_xor_sync(0xffffffffu, yp, 4);
        if (cg == 0) yout[(size_t)t * ND] = yp;
    }
}

// ---------------------------------------------------------------------------

extern "C" void kernel_launch(void* const* d_in, const int* in_sizes, int n_in,
                              void* d_out, int out_size)
{
    const float* x          = (const float*)d_in[0];
    const float* Wqkv_w     = (const float*)d_in[1];
    const float* Wqkv_b     = (const float*)d_in[2];
    const float* out_w      = (const float*)d_in[3];
    const float* out_b      = (const float*)d_in[4];
    const float* W_static   = (const float*)d_in[5];
    const float* Lambda_raw = (const float*)d_in[6];
    const float* Gamma      = (const float*)d_in[7];

    float* qkv = nullptr;
    float* y = nullptr;
    __nv_bfloat16 *sA = nullptr, *sB1 = nullptr, *sB2 = nullptr;
    cudaGetSymbolAddress((void**)&qkv, g_qkv);
    cudaGetSymbolAddress((void**)&y, g_y);
    cudaGetSymbolAddress((void**)&sA, g_sA);
    cudaGetSymbolAddress((void**)&sB1, g_sB1);
    cudaGetSymbolAddress((void**)&sB2, g_sB2);

    const long nx = (long)MTOT * ND;
    const long nw1 = (long)3 * ND * ND;
    const long nw2 = (long)ND * ND;

    // split x -> sA (A-side), Wqkv_w -> sB1 (B-side)
    split3_kernel<<<(unsigned)((nx / 4 + 255) / 256), 256>>>(x, sA, ND, nx, 0);
    split3_kernel<<<(unsigned)((nw1 / 4 + 255) / 256), 256>>>(Wqkv_w, sB1, ND, nw1, 1);
    // qkv = x @ Wqkv_w^T + b
    gemm_mma<<<dim3(3 * ND / 128, MTOT / 128), 256>>>(sA, sB1, Wqkv_b, qkv, 3 * ND, K3);

    // sequential STP scan -> y
    stp_scan<<<dim3(4, NB * NH), 128>>>(W_static, Lambda_raw, Gamma);

    // split y -> sA (A-side), out_w -> sB2 (B-side)
    split3_kernel<<<(unsigned)((nx / 4 + 255) / 256), 256>>>(y, sA, ND, nx, 0);
    split3_kernel<<<(unsigned)((nw2 / 4 + 255) / 256), 256>>>(out_w, sB2, ND, nw2, 1);
    // out = y @ out_w^T + b
    gemm_mma<<<dim3(ND / 128, MTOT / 128), 256>>>(sA, sB2, out_b, (float*)d_out, ND, K3);
}

// round 4
// speedup vs baseline: 2.3303x; 1.7241x over previous
#include <cuda_runtime.h>
#include <cuda_bf16.h>
#include <cstdint>

#define NB 4
#define NL 4096
#define NH 16
#define ND 1024
#define Nd 64
#define MTOT (NB * NL)          // 16384
#define K3 3072                 // 3 * 1024 (split-bf16 extended K)

// ---------------------------------------------------------------------------
// Device-global scratch (no allocations allowed)
// ---------------------------------------------------------------------------
__device__ float g_qkv[(size_t)NB * NL * 3 * ND];           // (B,L,3D) f32
__device__ float g_y[(size_t)NB * NL * ND];                 // (B,L,D)  f32
__device__ __nv_bfloat16 g_sA[(size_t)MTOT * K3];           // split A (x, then y)
__device__ __nv_bfloat16 g_sB1[(size_t)3 * ND * K3];        // split Wqkv_w
__device__ __nv_bfloat16 g_sB2[(size_t)ND * K3];            // split out_w

// ---------------------------------------------------------------------------
__device__ __forceinline__ uint32_t smem_u32(const void* p) {
    uint32_t a;
    asm("{ .reg .u64 t; cvta.to.shared.u64 t, %1; cvt.u32.u64 %0, t; }"
        : "=r"(a) : "l"(p));
    return a;
}

__device__ __forceinline__ void ldsm_x4(uint32_t* r, uint32_t addr) {
    asm volatile("ldmatrix.sync.aligned.m8n8.x4.shared.b16 {%0,%1,%2,%3}, [%4];"
                 : "=r"(r[0]), "=r"(r[1]), "=r"(r[2]), "=r"(r[3]) : "r"(addr));
}

__device__ __forceinline__ void mma_bf16(float* d, const uint32_t* a, const uint32_t* b) {
    asm volatile(
        "mma.sync.aligned.m16n8k16.row.col.f32.bf16.bf16.f32 "
        "{%0,%1,%2,%3}, {%4,%5,%6,%7}, {%8,%9}, {%0,%1,%2,%3};"
        : "+f"(d[0]), "+f"(d[1]), "+f"(d[2]), "+f"(d[3])
        : "r"(a[0]), "r"(a[1]), "r"(a[2]), "r"(a[3]), "r"(b[0]), "r"(b[1]));
}

__device__ __forceinline__ void cp16(uint32_t saddr, const void* gaddr) {
    asm volatile("cp.async.cg.shared.global [%0], [%1], 16;" :: "r"(saddr), "l"(gaddr));
}

// ---------------------------------------------------------------------------
// Split-bf16 conversion: src (R,K) f32 -> dst (R,3K) bf16.
//   A-side (bside=0): [hi | lo | hi];  B-side (bside=1): [hi | hi | lo]
// ---------------------------------------------------------------------------
__global__ __launch_bounds__(256) void split3_kernel(
    const float* __restrict__ src, __nv_bfloat16* __restrict__ dst,
    int K, long total, int bside)
{
    long i = ((long)blockIdx.x * blockDim.x + threadIdx.x) * 4;
    if (i >= total) return;
    float4 v = *(const float4*)(src + i);
    int r = (int)(i / K);
    int k = (int)(i - (long)r * K);
    float vv[4] = {v.x, v.y, v.z, v.w};
    __nv_bfloat16 hi[4], lo[4];
    #pragma unroll
    for (int j = 0; j < 4; j++) {
        hi[j] = __float2bfloat16(vv[j]);
        lo[j] = __float2bfloat16(vv[j] - __bfloat162float(hi[j]));
    }
    __nv_bfloat162 h01, h23, l01, l23;
    h01.x = hi[0]; h01.y = hi[1]; h23.x = hi[2]; h23.y = hi[3];
    l01.x = lo[0]; l01.y = lo[1]; l23.x = lo[2]; l23.y = lo[3];

    __nv_bfloat16* d0 = dst + (size_t)r * (3 * K) + k;
    *(__nv_bfloat162*)(d0)     = h01;
    *(__nv_bfloat162*)(d0 + 2) = h23;
    if (bside == 0) {
        *(__nv_bfloat162*)(d0 + K)         = l01;
        *(__nv_bfloat162*)(d0 + K + 2)     = l23;
        *(__nv_bfloat162*)(d0 + 2 * K)     = h01;
        *(__nv_bfloat162*)(d0 + 2 * K + 2) = h23;
    } else {
        *(__nv_bfloat162*)(d0 + K)         = h01;
        *(__nv_bfloat162*)(d0 + K + 2)     = h23;
        *(__nv_bfloat162*)(d0 + 2 * K)     = l01;
        *(__nv_bfloat162*)(d0 + 2 * K + 2) = l23;
    }
}

// ---------------------------------------------------------------------------
// mma.sync bf16 GEMM (unchanged from R3).
// ---------------------------------------------------------------------------
#define SMSTRIDE 40

__global__ __launch_bounds__(256, 1) void gemm_mma(
    const __nv_bfloat16* __restrict__ A, const __nv_bfloat16* __restrict__ Bw,
    const float* __restrict__ bias, float* __restrict__ C,
    int N, int K)
{
    __shared__ __align__(16) __nv_bfloat16 smA[2][128 * SMSTRIDE];
    __shared__ __align__(16) __nv_bfloat16 smB[2][128 * SMSTRIDE];

    const int tid = threadIdx.x;
    const int wid = tid >> 5;
    const int lane = tid & 31;
    const int wm = wid & 3;
    const int wn = wid >> 2;
    const int bm = blockIdx.y * 128;
    const int bn = blockIdx.x * 128;

    const int r0 = tid >> 2;
    const int sg = tid & 3;
    const __nv_bfloat16* Ag = A + (size_t)(bm + r0) * K + sg * 8;
    const __nv_bfloat16* Bg = Bw + (size_t)(bn + r0) * K + sg * 8;
    const uint32_t sAd = smem_u32(&smA[0][0]) + (uint32_t)(r0 * 80 + sg * 16);
    const uint32_t sBd = smem_u32(&smB[0][0]) + (uint32_t)(r0 * 80 + sg * 16);
    const size_t rowK64 = (size_t)64 * K;

    const int l15 = lane & 15;
    const uint32_t aBase = smem_u32(&smA[0][0])
        + (uint32_t)((wm * 32 + l15) * 80 + (lane >> 4) * 16);
    const int bnl = (lane & 7) + ((lane >> 4) & 1) * 8;
    const uint32_t bBase = smem_u32(&smB[0][0])
        + (uint32_t)((wn * 64 + bnl) * 80 + ((lane >> 3) & 1) * 16);

    float acc[2][8][4];
    #pragma unroll
    for (int mf = 0; mf < 2; mf++)
        #pragma unroll
        for (int nf = 0; nf < 8; nf++)
            #pragma unroll
            for (int j = 0; j < 4; j++)
                acc[mf][nf][j] = 0.0f;

    const int nch = K / 32;
    const uint32_t STAGE = 128 * 80;

    {
        cp16(sAd, Ag);
        cp16(sAd + 64 * 80, Ag + rowK64);
        cp16(sBd, Bg);
        cp16(sBd + 64 * 80, Bg + rowK64);
        asm volatile("cp.async.commit_group;" ::: "memory");
    }

    #pragma unroll 1
    for (int c = 0; c < nch; ++c) {
        if (c + 1 < nch) {
            const uint32_t so = ((c + 1) & 1) * STAGE;
            const __nv_bfloat16* Agn = Ag + (size_t)(c + 1) * 32;
            const __nv_bfloat16* Bgn = Bg + (size_t)(c + 1) * 32;
            cp16(sAd + so, Agn);
            cp16(sAd + so + 64 * 80, Agn + rowK64);
            cp16(sBd + so, Bgn);
            cp16(sBd + so + 64 * 80, Bgn + rowK64);
        }
        asm volatile("cp.async.commit_group;" ::: "memory");
        asm volatile("cp.async.wait_group 1;" ::: "memory");
        __syncthreads();

        const uint32_t so = (c & 1) * STAGE;
        const uint32_t aA = aBase + so;
        const uint32_t bA = bBase + so;

        #pragma unroll
        for (int ks = 0; ks < 2; ++ks) {
            uint32_t afr[2][4];
            ldsm_x4(afr[0], aA + ks * 32);
            ldsm_x4(afr[1], aA + 16 * 80 + ks * 32);
            uint32_t bfr[4][4];
            #pragma unroll
            for (int nq = 0; nq < 4; ++nq)
                ldsm_x4(bfr[nq], bA + nq * 16 * 80 + ks * 32);

            #pragma unroll
            for (int mf = 0; mf < 2; ++mf)
                #pragma unroll
                for (int nf = 0; nf < 8; ++nf)
                    mma_bf16(acc[mf][nf], afr[mf], &bfr[nf >> 1][(nf & 1) * 2]);
        }
        __syncthreads();
    }

    const int erow = lane >> 2;
    const int ecol = (lane & 3) * 2;
    #pragma unroll
    for (int mf = 0; mf < 2; ++mf) {
        const int row = bm + wm * 32 + mf * 16 + erow;
        #pragma unroll
        for (int nf = 0; nf < 8; ++nf) {
            const int col = bn + wn * 64 + nf * 8 + ecol;
            float2 bb = *(const float2*)(bias + col);
            float2 o0, o1;
            o0.x = acc[mf][nf][0] + bb.x;
            o0.y = acc[mf][nf][1] + bb.y;
            o1.x = acc[mf][nf][2] + bb.x;
            o1.y = acc[mf][nf][3] + bb.y;
            *(float2*)(C + (size_t)row * N + col) = o0;
            *(float2*)(C + (size_t)(row + 8) * N + col) = o1;
        }
    }
}

// ---------------------------------------------------------------------------
// STP scan, chunked smem staging.
// Block = 128 threads = 4 warps, covers 16 rows of one (b,h).
// Each chunk = 64 time-steps staged via cp.async (double-buffered):
//   q[64][64], k[64][64] (f32) + v[64][16].
// Lane layout (unchanged): warp = 4 rows x 64 cols, lane=(rg[2b],cg[3b]),
// 8 cols per lane. 3-shfl reduction deferred one step for latency overlap.
// smem bytes: q 2*16384, k 2*16384, v 2*4096 = 73728.
// ---------------------------------------------------------------------------
#define TCH 64
#define NCH (NL / TCH)          // 64
#define SCAN_SMEM 73728

__global__ __launch_bounds__(128) void stp_scan(
    const float* __restrict__ Wst,
    const float* __restrict__ Lam,
    const float* __restrict__ Gam)
{
    extern __shared__ __align__(16) float sm[];
    // layout (bytes): q: [0, 32768) two stages of 16384; k: [32768, 65536); v: [65536, 73728)
    const uint32_t smb = smem_u32(sm);

    const int bh = blockIdx.y;
    const int b = bh >> 4;
    const int h = bh & 15;
    const int tid = threadIdx.x;
    const int w = tid >> 5;
    const int lane = tid & 31;
    const int rg = lane >> 3;
    const int cg = lane & 7;
    const int row0 = blockIdx.x << 4;        // block's first row within head
    const int rloc = (w << 2) + rg;          // row within block 0..15
    const int i = row0 + rloc;               // row within head 0..63
    const int j0 = cg << 3;

    // per-lane constants
    float u[8], r[8], g[8], cw[8];
    {
        const int pbase = (h * Nd + i) * Nd + j0;
        float4 wa = *(const float4*)(Wst + pbase);
        float4 wb = *(const float4*)(Wst + pbase + 4);
        float4 la = *(const float4*)(Lam + pbase);
        float4 lb = *(const float4*)(Lam + pbase + 4);
        float4 ga = *(const float4*)(Gam + pbase);
        float4 gb = *(const float4*)(Gam + pbase + 4);
        float wv[8] = {wa.x, wa.y, wa.z, wa.w, wb.x, wb.y, wb.z, wb.w};
        float lv[8] = {la.x, la.y, la.z, la.w, lb.x, lb.y, lb.z, lb.w};
        float gv[8] = {ga.x, ga.y, ga.z, ga.w, gb.x, gb.y, gb.z, gb.w};
        #pragma unroll
        for (int jj = 0; jj < 8; jj++) {
            float sg = 1.0f / (1.0f + __expf(-lv[jj]));
            r[jj] = 1.0f - sg;
            cw[jj] = sg * wv[jj];
            u[jj] = wv[jj];
            g[jj] = gv[jj] * 0.125f;
        }
    }

    const float* gq = g_qkv + (size_t)b * NL * 3 * ND + h * Nd;  // head base
    float* yout = g_y + (size_t)b * NL * ND + h * Nd + i;

    // ---- chunk loader: stage s, starting step t0 ----
    auto load_chunk = [&](int s, int t0) {
        const uint32_t qb = smb + (uint32_t)s * 16384u;
        const uint32_t kb = smb + 32768u + (uint32_t)s * 16384u;
        const uint32_t vb = smb + 65536u + (uint32_t)s * 4096u;
        #pragma unroll
        for (int it = 0; it < 8; ++it) {
            int idx = tid + (it << 7);
            int st = idx >> 4;
            int seg = (idx & 15) << 2;          // float offset
            const float* src = gq + (size_t)(t0 + st) * (3 * ND) + seg;
            uint32_t o = (uint32_t)((st << 6) + seg) << 2;
            cp16(qb + o, src);
            cp16(kb + o, src + ND);
        }
        #pragma unroll
        for (int it = 0; it < 2; ++it) {
            int idx = tid + (it << 7);
            int st = idx >> 2;
            int sg4 = (idx & 3) << 2;
            const float* src = gq + (size_t)(t0 + st) * (3 * ND) + 2 * ND + row0 + sg4;
            cp16(vb + (uint32_t)(((st << 4) + sg4) << 2), src);
        }
        asm volatile("cp.async.commit_group;" ::: "memory");
    };

    // prologue
    load_chunk(0, 0);

    float pend = 0.0f;

    #pragma unroll 1
    for (int c = 0; c < NCH; ++c) {
        if (c + 1 < NCH) {
            load_chunk((c + 1) & 1, (c + 1) * TCH);
            asm volatile("cp.async.wait_group 1;" ::: "memory");
        } else {
            asm volatile("cp.async.wait_group 0;" ::: "memory");
        }
        __syncthreads();

        const int s = c & 1;
        const float* qs = (const float*)(sm) + s * 4096;
        const float* ks = (const float*)(sm) + 8192 + s * 4096;
        const float* vs = (const float*)(sm) + 16384 + s * 1024;

        #pragma unroll 4
        for (int tt = 0; tt < TCH; ++tt) {
            const int t = c * TCH + tt;
            float4 qa = *(const float4*)(qs + (tt << 6) + j0);
            float4 qb2 = *(const float4*)(qs + (tt << 6) + j0 + 4);
            float4 ka = *(const float4*)(ks + (tt << 6) + j0);
            float4 kb2 = *(const float4*)(ks + (tt << 6) + j0 + 4);
            const float cv = vs[(tt << 4) + rloc];

            const float kv[8] = {ka.x, ka.y, ka.z, ka.w, kb2.x, kb2.y, kb2.z, kb2.w};
            const float qv[8] = {qa.x, qa.y, qa.z, qa.w, qb2.x, qb2.y, qb2.z, qb2.w};

            float yp = 0.0f;
            #pragma unroll
            for (int jj = 0; jj < 8; jj++) {
                float vk = cv * kv[jj];
                float tmp = fmaf(g[jj], vk, cw[jj]);
                u[jj] = fmaf(r[jj], u[jj], tmp);
                yp = fmaf(u[jj], qv[jj], yp);
            }

            // deferred reduction/store of previous step (overlaps shfl latency)
            if (t > 0) {
                float rsum = pend + __shfl_xor_sync(0xffffffffu, pend, 1);
                rsum += __shfl_xor_sync(0xffffffffu, rsum, 2);
                rsum += __shfl_xor_sync(0xffffffffu, rsum, 4);
                if (cg == 0) yout[(size_t)(t - 1) * ND] = rsum;
            }
            pend = yp;
        }
        __syncthreads();   // protect stage before it is overwritten
    }

    // flush final step
    {
        float rsum = pend + __shfl_xor_sync(0xffffffffu, pend, 1);
        rsum += __shfl_xor_sync(0xffffffffu, rsum, 2);
        rsum += __shfl_xor_sync(0xffffffffu, rsum, 4);
        if (cg == 0) yout[(size_t)(NL - 1) * ND] = rsum;
    }
}

// ---------------------------------------------------------------------------

extern "C" void kernel_launch(void* const* d_in, const int* in_sizes, int n_in,
                              void* d_out, int out_size)
{
    const float* x          = (const float*)d_in[0];
    const float* Wqkv_w     = (const float*)d_in[1];
    const float* Wqkv_b     = (const float*)d_in[2];
    const float* out_w      = (const float*)d_in[3];
    const float* out_b      = (const float*)d_in[4];
    const float* W_static   = (const float*)d_in[5];
    const float* Lambda_raw = (const float*)d_in[6];
    const float* Gamma      = (const float*)d_in[7];

    float* qkv = nullptr;
    float* y = nullptr;
    __nv_bfloat16 *sA = nullptr, *sB1 = nullptr, *sB2 = nullptr;
    cudaGetSymbolAddress((void**)&qkv, g_qkv);
    cudaGetSymbolAddress((void**)&y, g_y);
    cudaGetSymbolAddress((void**)&sA, g_sA);
    cudaGetSymbolAddress((void**)&sB1, g_sB1);
    cudaGetSymbolAddress((void**)&sB2, g_sB2);

    static bool attr_set = false;
    if (!attr_set) {
        cudaFuncSetAttribute(stp_scan, cudaFuncAttributeMaxDynamicSharedMemorySize, SCAN_SMEM);
        attr_set = true;
    }

    const long nx = (long)MTOT * ND;
    const long nw1 = (long)3 * ND * ND;
    const long nw2 = (long)ND * ND;

    // split x -> sA (A-side), Wqkv_w -> sB1 (B-side)
    split3_kernel<<<(unsigned)((nx / 4 + 255) / 256), 256>>>(x, sA, ND, nx, 0);
    split3_kernel<<<(unsigned)((nw1 / 4 + 255) / 256), 256>>>(Wqkv_w, sB1, ND, nw1, 1);
    // qkv = x @ Wqkv_w^T + b
    gemm_mma<<<dim3(3 * ND / 128, MTOT / 128), 256>>>(sA, sB1, Wqkv_b, qkv, 3 * ND, K3);

    // sequential STP scan -> y
    stp_scan<<<dim3(4, NB * NH), 128, SCAN_SMEM>>>(W_static, Lambda_raw, Gamma);

    // split y -> sA (A-side), out_w -> sB2 (B-side)
    split3_kernel<<<(unsigned)((nx / 4 + 255) / 256), 256>>>(y, sA, ND, nx, 0);
    split3_kernel<<<(unsigned)((nw2 / 4 + 255) / 256), 256>>>(out_w, sB2, ND, nw2, 1);
    // out = y @ out_w^T + b
    gemm_mma<<<dim3(ND / 128, MTOT / 128), 256>>>(sA, sB2, out_b, (float*)d_out, ND, K3);
}

// round 5
// speedup vs baseline: 2.4429x; 1.0483x over previous
#include <cuda_runtime.h>
#include <cuda_bf16.h>
#include <cstdint>

#define NB 4
#define NL 4096
#define NH 16
#define ND 1024
#define Nd 64
#define MTOT (NB * NL)          // 16384
#define K3 3072                 // 3 * 1024 (split-bf16 extended K)

// ---------------------------------------------------------------------------
// Device-global scratch (no allocations allowed)
// ---------------------------------------------------------------------------
__device__ float g_qkv[(size_t)NB * NL * 3 * ND];
__device__ float g_y[(size_t)NB * NL * ND];
__device__ __nv_bfloat16 g_sA[(size_t)MTOT * K3];
__device__ __nv_bfloat16 g_sB1[(size_t)3 * ND * K3];
__device__ __nv_bfloat16 g_sB2[(size_t)ND * K3];

// ---------------------------------------------------------------------------
__device__ __forceinline__ uint32_t smem_u32(const void* p) {
    uint32_t a;
    asm("{ .reg .u64 t; cvta.to.shared.u64 t, %1; cvt.u32.u64 %0, t; }"
        : "=r"(a) : "l"(p));
    return a;
}

__device__ __forceinline__ void ldsm_x4(uint32_t* r, uint32_t addr) {
    asm volatile("ldmatrix.sync.aligned.m8n8.x4.shared.b16 {%0,%1,%2,%3}, [%4];"
                 : "=r"(r[0]), "=r"(r[1]), "=r"(r[2]), "=r"(r[3]) : "r"(addr));
}

__device__ __forceinline__ void mma_bf16(float* d, const uint32_t* a, const uint32_t* b) {
    asm volatile(
        "mma.sync.aligned.m16n8k16.row.col.f32.bf16.bf16.f32 "
        "{%0,%1,%2,%3}, {%4,%5,%6,%7}, {%8,%9}, {%0,%1,%2,%3};"
        : "+f"(d[0]), "+f"(d[1]), "+f"(d[2]), "+f"(d[3])
        : "r"(a[0]), "r"(a[1]), "r"(a[2]), "r"(a[3]), "r"(b[0]), "r"(b[1]));
}

__device__ __forceinline__ void cp16(uint32_t saddr, const void* gaddr) {
    asm volatile("cp.async.cg.shared.global [%0], [%1], 16;" :: "r"(saddr), "l"(gaddr));
}

// f32x2 packed math (sm_100+ family-common PTX)
__device__ __forceinline__ uint64_t mul2(uint64_t a, uint64_t b) {
    uint64_t d;
    asm("mul.rn.f32x2 %0, %1, %2;" : "=l"(d) : "l"(a), "l"(b));
    return d;
}
__device__ __forceinline__ uint64_t fma2(uint64_t a, uint64_t b, uint64_t c) {
    uint64_t d;
    asm("fma.rn.f32x2 %0, %1, %2, %3;" : "=l"(d) : "l"(a), "l"(b), "l"(c));
    return d;
}
__device__ __forceinline__ uint64_t pack2(float lo, float hi) {
    uint64_t d;
    asm("mov.b64 %0, {%1, %2};" : "=l"(d) : "r"(__float_as_uint(lo)), "r"(__float_as_uint(hi)));
    return d;
}
__device__ __forceinline__ float hadd2(uint64_t v) {
    uint32_t lo, hi;
    asm("mov.b64 {%0, %1}, %2;" : "=r"(lo), "=r"(hi) : "l"(v));
    return __uint_as_float(lo) + __uint_as_float(hi);
}

// ---------------------------------------------------------------------------
// Split-bf16 conversion: src (R,K) f32 -> dst (R,3K) bf16.
//   A-side (bside=0): [hi | lo | hi];  B-side (bside=1): [hi | hi | lo]
// ---------------------------------------------------------------------------
__global__ __launch_bounds__(256) void split3_kernel(
    const float* __restrict__ src, __nv_bfloat16* __restrict__ dst,
    int K, long total, int bside)
{
    long i = ((long)blockIdx.x * blockDim.x + threadIdx.x) * 4;
    if (i >= total) return;
    float4 v = *(const float4*)(src + i);
    int r = (int)(i / K);
    int k = (int)(i - (long)r * K);
    float vv[4] = {v.x, v.y, v.z, v.w};
    __nv_bfloat16 hi[4], lo[4];
    #pragma unroll
    for (int j = 0; j < 4; j++) {
        hi[j] = __float2bfloat16(vv[j]);
        lo[j] = __float2bfloat16(vv[j] - __bfloat162float(hi[j]));
    }
    __nv_bfloat162 h01, h23, l01, l23;
    h01.x = hi[0]; h01.y = hi[1]; h23.x = hi[2]; h23.y = hi[3];
    l01.x = lo[0]; l01.y = lo[1]; l23.x = lo[2]; l23.y = lo[3];

    __nv_bfloat16* d0 = dst + (size_t)r * (3 * K) + k;
    *(__nv_bfloat162*)(d0)     = h01;
    *(__nv_bfloat162*)(d0 + 2) = h23;
    if (bside == 0) {
        *(__nv_bfloat162*)(d0 + K)         = l01;
        *(__nv_bfloat162*)(d0 + K + 2)     = l23;
        *(__nv_bfloat162*)(d0 + 2 * K)     = h01;
        *(__nv_bfloat162*)(d0 + 2 * K + 2) = h23;
    } else {
        *(__nv_bfloat162*)(d0 + K)         = h01;
        *(__nv_bfloat162*)(d0 + K + 2)     = h23;
        *(__nv_bfloat162*)(d0 + 2 * K)     = l01;
        *(__nv_bfloat162*)(d0 + 2 * K + 2) = l23;
    }
}

// ---------------------------------------------------------------------------
// mma.sync bf16 GEMM, 4-stage cp.async pipeline, dynamic smem (80 KB).
// 128x128 CTA tile, BK=32, 8 warps (4m x 2n), warp tile 32x64.
// Stage layout: stage s at s*20480; A [0,10240), B [10240,20480); 80B rows.
// ---------------------------------------------------------------------------
#define GSTAGE 20480
#define GEMM_SMEM (4 * GSTAGE)

__global__ __launch_bounds__(256, 1) void gemm_mma(
    const __nv_bfloat16* __restrict__ A, const __nv_bfloat16* __restrict__ Bw,
    const float* __restrict__ bias, float* __restrict__ C,
    int N, int K)
{
    extern __shared__ __align__(16) char dsm[];
    const uint32_t smb = smem_u32(dsm);

    const int tid = threadIdx.x;
    const int wid = tid >> 5;
    const int lane = tid & 31;
    const int wm = wid & 3;
    const int wn = wid >> 2;
    const int bm = blockIdx.y * 128;
    const int bn = blockIdx.x * 128;

    const int r0 = tid >> 2;
    const int sg = tid & 3;
    const __nv_bfloat16* Ag = A + (size_t)(bm + r0) * K + sg * 8;
    const __nv_bfloat16* Bg = Bw + (size_t)(bn + r0) * K + sg * 8;
    const uint32_t ldOff = (uint32_t)(r0 * 80 + sg * 16);
    const size_t rowK64 = (size_t)64 * K;

    const int l15 = lane & 15;
    const uint32_t aOff = (uint32_t)((wm * 32 + l15) * 80 + (lane >> 4) * 16);
    const int bnl = (lane & 7) + ((lane >> 4) & 1) * 8;
    const uint32_t bOff = 10240u + (uint32_t)((wn * 64 + bnl) * 80 + ((lane >> 3) & 1) * 16);

    float acc[2][8][4];
    #pragma unroll
    for (int mf = 0; mf < 2; mf++)
        #pragma unroll
        for (int nf = 0; nf < 8; nf++)
            #pragma unroll
            for (int j = 0; j < 4; j++)
                acc[mf][nf][j] = 0.0f;

    const int nch = K / 32;

    auto load_chunk = [&](int s, int ch) {
        const uint32_t stg = smb + (uint32_t)s * GSTAGE;
        const __nv_bfloat16* Ac = Ag + (size_t)ch * 32;
        const __nv_bfloat16* Bc = Bg + (size_t)ch * 32;
        cp16(stg + ldOff, Ac);
        cp16(stg + ldOff + 64 * 80, Ac + rowK64);
        cp16(stg + 10240 + ldOff, Bc);
        cp16(stg + 10240 + ldOff + 64 * 80, Bc + rowK64);
    };

    // prologue: stages 0..2
    #pragma unroll
    for (int p = 0; p < 3; ++p) {
        load_chunk(p, p);
        asm volatile("cp.async.commit_group;" ::: "memory");
    }

    #pragma unroll 1
    for (int c = 0; c < nch; ++c) {
        asm volatile("cp.async.wait_group 2;" ::: "memory");
        __syncthreads();

        if (c + 3 < nch) load_chunk((c + 3) & 3, c + 3);
        asm volatile("cp.async.commit_group;" ::: "memory");

        const uint32_t so = smb + (uint32_t)(c & 3) * GSTAGE;
        const uint32_t aA = so + aOff;
        const uint32_t bA = so + bOff;

        #pragma unroll
        for (int ks = 0; ks < 2; ++ks) {
            uint32_t afr[2][4];
            ldsm_x4(afr[0], aA + ks * 32);
            ldsm_x4(afr[1], aA + 16 * 80 + ks * 32);
            uint32_t bfr[4][4];
            #pragma unroll
            for (int nq = 0; nq < 4; ++nq)
                ldsm_x4(bfr[nq], bA + nq * 16 * 80 + ks * 32);

            #pragma unroll
            for (int mf = 0; mf < 2; ++mf)
                #pragma unroll
                for (int nf = 0; nf < 8; ++nf)
                    mma_bf16(acc[mf][nf], afr[mf], &bfr[nf >> 1][(nf & 1) * 2]);
        }
    }

    __syncthreads();

    const int erow = lane >> 2;
    const int ecol = (lane & 3) * 2;
    #pragma unroll
    for (int mf = 0; mf < 2; ++mf) {
        const int row = bm + wm * 32 + mf * 16 + erow;
        #pragma unroll
        for (int nf = 0; nf < 8; ++nf) {
            const int col = bn + wn * 64 + nf * 8 + ecol;
            float2 bb = *(const float2*)(bias + col);
            float2 o0, o1;
            o0.x = acc[mf][nf][0] + bb.x;
            o0.y = acc[mf][nf][1] + bb.y;
            o1.x = acc[mf][nf][2] + bb.x;
            o1.y = acc[mf][nf][3] + bb.y;
            *(float2*)(C + (size_t)row * N + col) = o0;
            *(float2*)(C + (size_t)(row + 8) * N + col) = o1;
        }
    }
}

// ---------------------------------------------------------------------------
// STP scan: chunked smem staging + f32x2 packed math + 8-step batched shfl.
// Block = 128 threads (4 warps) = 16 rows of one (b,h).
// ---------------------------------------------------------------------------
#define TCH 64
#define NCH (NL / TCH)
#define SCAN_SMEM 73728

__global__ __launch_bounds__(128) void stp_scan(
    const float* __restrict__ Wst,
    const float* __restrict__ Lam,
    const float* __restrict__ Gam)
{
    extern __shared__ __align__(16) float sm[];
    const uint32_t smb = smem_u32(sm);

    const int bh = blockIdx.y;
    const int b = bh >> 4;
    const int h = bh & 15;
    const int tid = threadIdx.x;
    const int w = tid >> 5;
    const int lane = tid & 31;
    const int rg = lane >> 3;
    const int cg = lane & 7;
    const int row0 = blockIdx.x << 4;
    const int rloc = (w << 2) + rg;
    const int i = row0 + rloc;
    const int j0 = cg << 3;

    // per-lane constants as packed f32x2 pairs
    uint64_t u2[4], r2[4], g2[4], cw2[4];
    {
        const int pbase = (h * Nd + i) * Nd + j0;
        float wv[8], lv[8], gv[8];
        *(float4*)(wv)     = *(const float4*)(Wst + pbase);
        *(float4*)(wv + 4) = *(const float4*)(Wst + pbase + 4);
        *(float4*)(lv)     = *(const float4*)(Lam + pbase);
        *(float4*)(lv + 4) = *(const float4*)(Lam + pbase + 4);
        *(float4*)(gv)     = *(const float4*)(Gam + pbase);
        *(float4*)(gv + 4) = *(const float4*)(Gam + pbase + 4);
        float uu[8], rr[8], gg[8], cc[8];
        #pragma unroll
        for (int jj = 0; jj < 8; jj++) {
            float sgm = 1.0f / (1.0f + __expf(-lv[jj]));
            rr[jj] = 1.0f - sgm;
            cc[jj] = sgm * wv[jj];
            uu[jj] = wv[jj];
            gg[jj] = gv[jj] * 0.125f;
        }
        #pragma unroll
        for (int p = 0; p < 4; p++) {
            u2[p]  = pack2(uu[2 * p], uu[2 * p + 1]);
            r2[p]  = pack2(rr[2 * p], rr[2 * p + 1]);
            g2[p]  = pack2(gg[2 * p], gg[2 * p + 1]);
            cw2[p] = pack2(cc[2 * p], cc[2 * p + 1]);
        }
    }

    const float* gq = g_qkv + (size_t)b * NL * 3 * ND + h * Nd;
    float* yout = g_y + (size_t)b * NL * ND + h * Nd + i;

    auto load_chunk = [&](int s, int t0) {
        const uint32_t qb = smb + (uint32_t)s * 16384u;
        const uint32_t kb = smb + 32768u + (uint32_t)s * 16384u;
        const uint32_t vb = smb + 65536u + (uint32_t)s * 4096u;
        #pragma unroll
        for (int it = 0; it < 8; ++it) {
            int idx = tid + (it << 7);
            int st = idx >> 4;
            int seg = (idx & 15) << 2;
            const float* src = gq + (size_t)(t0 + st) * (3 * ND) + seg;
            uint32_t o = (uint32_t)((st << 6) + seg) << 2;
            cp16(qb + o, src);
            cp16(kb + o, src + ND);
        }
        #pragma unroll
        for (int it = 0; it < 2; ++it) {
            int idx = tid + (it << 7);
            int st = idx >> 2;
            int sg4 = (idx & 3) << 2;
            const float* src = gq + (size_t)(t0 + st) * (3 * ND) + 2 * ND + row0 + sg4;
            cp16(vb + (uint32_t)(((st << 4) + sg4) << 2), src);
        }
        asm volatile("cp.async.commit_group;" ::: "memory");
    };

    load_chunk(0, 0);

    #pragma unroll 1
    for (int c = 0; c < NCH; ++c) {
        if (c + 1 < NCH) {
            load_chunk((c + 1) & 1, (c + 1) * TCH);
            asm volatile("cp.async.wait_group 1;" ::: "memory");
        } else {
            asm volatile("cp.async.wait_group 0;" ::: "memory");
        }
        __syncthreads();

        const int s = c & 1;
        const float* qs = (const float*)(sm) + s * 4096;
        const float* ks = (const float*)(sm) + 8192 + s * 4096;
        const float* vs = (const float*)(sm) + 16384 + s * 1024;

        #pragma unroll 1
        for (int tt0 = 0; tt0 < TCH; tt0 += 8) {
            float yps[8];
            #pragma unroll
            for (int ss = 0; ss < 8; ++ss) {
                const int tt = tt0 + ss;
                const ulonglong2 qA = *(const ulonglong2*)(qs + (tt << 6) + j0);
                const ulonglong2 qB = *(const ulonglong2*)(qs + (tt << 6) + j0 + 4);
                const ulonglong2 kA = *(const ulonglong2*)(ks + (tt << 6) + j0);
                const ulonglong2 kB = *(const ulonglong2*)(ks + (tt << 6) + j0 + 4);
                const float cv = vs[(tt << 4) + rloc];
                const uint64_t v2 = pack2(cv, cv);
                const uint64_t q2[4] = {qA.x, qA.y, qB.x, qB.y};
                const uint64_t k2[4] = {kA.x, kA.y, kB.x, kB.y};

                uint64_t acc = 0ull;
                #pragma unroll
                for (int p = 0; p < 4; ++p) {
                    uint64_t vk = mul2(v2, k2[p]);
                    uint64_t tmp = fma2(g2[p], vk, cw2[p]);
                    u2[p] = fma2(r2[p], u2[p], tmp);
                    acc = fma2(u2[p], q2[p], acc);
                }
                yps[ss] = hadd2(acc);
            }

            // batched 3-level butterfly over the 8 col-group lanes
            #pragma unroll
            for (int ss = 0; ss < 8; ++ss) yps[ss] += __shfl_xor_sync(0xffffffffu, yps[ss], 1);
            #pragma unroll
            for (int ss = 0; ss < 8; ++ss) yps[ss] += __shfl_xor_sync(0xffffffffu, yps[ss], 2);
            #pragma unroll
            for (int ss = 0; ss < 8; ++ss) yps[ss] += __shfl_xor_sync(0xffffffffu, yps[ss], 4);

            if (cg == 0) {
                const size_t t0 = (size_t)c * TCH + tt0;
                #pragma unroll
                for (int ss = 0; ss < 8; ++ss)
                    yout[(t0 + ss) * ND] = yps[ss];
            }
        }
        __syncthreads();
    }
}

// ---------------------------------------------------------------------------

extern "C" void kernel_launch(void* const* d_in, const int* in_sizes, int n_in,
                              void* d_out, int out_size)
{
    const float* x          = (const float*)d_in[0];
    const float* Wqkv_w     = (const float*)d_in[1];
    const float* Wqkv_b     = (const float*)d_in[2];
    const float* out_w      = (const float*)d_in[3];
    const float* out_b      = (const float*)d_in[4];
    const float* W_static   = (const float*)d_in[5];
    const float* Lambda_raw = (const float*)d_in[6];
    const float* Gamma      = (const float*)d_in[7];

    float* qkv = nullptr;
    float* y = nullptr;
    __nv_bfloat16 *sA = nullptr, *sB1 = nullptr, *sB2 = nullptr;
    cudaGetSymbolAddress((void**)&qkv, g_qkv);
    cudaGetSymbolAddress((void**)&y, g_y);
    cudaGetSymbolAddress((void**)&sA, g_sA);
    cudaGetSymbolAddress((void**)&sB1, g_sB1);
    cudaGetSymbolAddress((void**)&sB2, g_sB2);

    static bool attr_set = false;
    if (!attr_set) {
        cudaFuncSetAttribute(stp_scan, cudaFuncAttributeMaxDynamicSharedMemorySize, SCAN_SMEM);
        cudaFuncSetAttribute(gemm_mma, cudaFuncAttributeMaxDynamicSharedMemorySize, GEMM_SMEM);
        attr_set = true;
    }

    const long nx = (long)MTOT * ND;
    const long nw1 = (long)3 * ND * ND;
    const long nw2 = (long)ND * ND;

    split3_kernel<<<(unsigned)((nx / 4 + 255) / 256), 256>>>(x, sA, ND, nx, 0);
    split3_kernel<<<(unsigned)((nw1 / 4 + 255) / 256), 256>>>(Wqkv_w, sB1, ND, nw1, 1);
    gemm_mma<<<dim3(3 * ND / 128, MTOT / 128), 256, GEMM_SMEM>>>(sA, sB1, Wqkv_b, qkv, 3 * ND, K3);

    stp_scan<<<dim3(4, NB * NH), 128, SCAN_SMEM>>>(W_static, Lambda_raw, Gamma);

    split3_kernel<<<(unsigned)((nx / 4 + 255) / 256), 256>>>(y, sA, ND, nx, 0);
    split3_kernel<<<(unsigned)((nw2 / 4 + 255) / 256), 256>>>(out_w, sB2, ND, nw2, 1);
    gemm_mma<<<dim3(ND / 128, MTOT / 128), 256, GEMM_SMEM>>>(sA, sB2, out_b, (float*)d_out, ND, K3);
}

// round 6
// speedup vs baseline: 2.7823x; 1.1389x over previous
#include <cuda_runtime.h>
#include <cuda_bf16.h>
#include <cstdint>

#define NB 4
#define NL 4096
#define NH 16
#define ND 1024
#define Nd 64
#define MTOT (NB * NL)          // 16384
#define K3 3072                 // 3 * 1024 (split-bf16 extended K)
#define SEG 1024                // time-segment length (NL / 4)

// ---------------------------------------------------------------------------
// Device-global scratch (no allocations allowed)
// ---------------------------------------------------------------------------
__device__ float g_qkv[(size_t)NB * NL * 3 * ND];
__device__ float g_y[(size_t)NB * NL * ND];
__device__ float g_fst[(size_t)3 * 64 * 4096];      // segment-final local states
__device__ __nv_bfloat16 g_sA[(size_t)MTOT * K3];
__device__ __nv_bfloat16 g_sB1[(size_t)3 * ND * K3];
__device__ __nv_bfloat16 g_sB2[(size_t)ND * K3];

// ---------------------------------------------------------------------------
__device__ __forceinline__ uint32_t smem_u32(const void* p) {
    uint32_t a;
    asm("{ .reg .u64 t; cvta.to.shared.u64 t, %1; cvt.u32.u64 %0, t; }"
        : "=r"(a) : "l"(p));
    return a;
}
__device__ __forceinline__ void ldsm_x4(uint32_t* r, uint32_t addr) {
    asm volatile("ldmatrix.sync.aligned.m8n8.x4.shared.b16 {%0,%1,%2,%3}, [%4];"
                 : "=r"(r[0]), "=r"(r[1]), "=r"(r[2]), "=r"(r[3]) : "r"(addr));
}
__device__ __forceinline__ void mma_bf16(float* d, const uint32_t* a, const uint32_t* b) {
    asm volatile(
        "mma.sync.aligned.m16n8k16.row.col.f32.bf16.bf16.f32 "
        "{%0,%1,%2,%3}, {%4,%5,%6,%7}, {%8,%9}, {%0,%1,%2,%3};"
        : "+f"(d[0]), "+f"(d[1]), "+f"(d[2]), "+f"(d[3])
        : "r"(a[0]), "r"(a[1]), "r"(a[2]), "r"(a[3]), "r"(b[0]), "r"(b[1]));
}
__device__ __forceinline__ void cp16(uint32_t saddr, const void* gaddr) {
    asm volatile("cp.async.cg.shared.global [%0], [%1], 16;" :: "r"(saddr), "l"(gaddr));
}
__device__ __forceinline__ uint64_t mul2(uint64_t a, uint64_t b) {
    uint64_t d; asm("mul.rn.f32x2 %0, %1, %2;" : "=l"(d) : "l"(a), "l"(b)); return d;
}
__device__ __forceinline__ uint64_t fma2(uint64_t a, uint64_t b, uint64_t c) {
    uint64_t d; asm("fma.rn.f32x2 %0, %1, %2, %3;" : "=l"(d) : "l"(a), "l"(b), "l"(c)); return d;
}
__device__ __forceinline__ uint64_t pack2(float lo, float hi) {
    uint64_t d;
    asm("mov.b64 %0, {%1, %2};" : "=l"(d) : "r"(__float_as_uint(lo)), "r"(__float_as_uint(hi)));
    return d;
}
__device__ __forceinline__ float hadd2(uint64_t v) {
    uint32_t lo, hi;
    asm("mov.b64 {%0, %1}, %2;" : "=r"(lo), "=r"(hi) : "l"(v));
    return __uint_as_float(lo) + __uint_as_float(hi);
}
__device__ __forceinline__ void unpack2(float& lo, float& hi, uint64_t v) {
    uint32_t l, h;
    asm("mov.b64 {%0, %1}, %2;" : "=r"(l), "=r"(h) : "l"(v));
    lo = __uint_as_float(l); hi = __uint_as_float(h);
}

// ---------------------------------------------------------------------------
// Split-bf16 conversion: src (R,K) f32 -> dst (R,3K) bf16.
// ---------------------------------------------------------------------------
__global__ __launch_bounds__(256) void split3_kernel(
    const float* __restrict__ src, __nv_bfloat16* __restrict__ dst,
    int K, long total, int bside)
{
    long i = ((long)blockIdx.x * blockDim.x + threadIdx.x) * 4;
    if (i >= total) return;
    float4 v = *(const float4*)(src + i);
    int r = (int)(i / K);
    int k = (int)(i - (long)r * K);
    float vv[4] = {v.x, v.y, v.z, v.w};
    __nv_bfloat16 hi[4], lo[4];
    #pragma unroll
    for (int j = 0; j < 4; j++) {
        hi[j] = __float2bfloat16(vv[j]);
        lo[j] = __float2bfloat16(vv[j] - __bfloat162float(hi[j]));
    }
    __nv_bfloat162 h01, h23, l01, l23;
    h01.x = hi[0]; h01.y = hi[1]; h23.x = hi[2]; h23.y = hi[3];
    l01.x = lo[0]; l01.y = lo[1]; l23.x = lo[2]; l23.y = lo[3];

    __nv_bfloat16* d0 = dst + (size_t)r * (3 * K) + k;
    *(__nv_bfloat162*)(d0)     = h01;
    *(__nv_bfloat162*)(d0 + 2) = h23;
    if (bside == 0) {
        *(__nv_bfloat162*)(d0 + K)         = l01;
        *(__nv_bfloat162*)(d0 + K + 2)     = l23;
        *(__nv_bfloat162*)(d0 + 2 * K)     = h01;
        *(__nv_bfloat162*)(d0 + 2 * K + 2) = h23;
    } else {
        *(__nv_bfloat162*)(d0 + K)         = h01;
        *(__nv_bfloat162*)(d0 + K + 2)     = h23;
        *(__nv_bfloat162*)(d0 + 2 * K)     = l01;
        *(__nv_bfloat162*)(d0 + 2 * K + 2) = l23;
    }
}

// ---------------------------------------------------------------------------
// mma.sync bf16 GEMM, 3-stage cp.async pipeline, 60KB smem, 2 CTAs/SM.
// ---------------------------------------------------------------------------
#define GSTAGE 20480
#define GEMM_SMEM (3 * GSTAGE)

__global__ __launch_bounds__(256, 2) void gemm_mma(
    const __nv_bfloat16* __restrict__ A, const __nv_bfloat16* __restrict__ Bw,
    const float* __restrict__ bias, float* __restrict__ C,
    int N, int K)
{
    extern __shared__ __align__(16) char dsm[];
    const uint32_t smb = smem_u32(dsm);

    const int tid = threadIdx.x;
    const int wid = tid >> 5;
    const int lane = tid & 31;
    const int wm = wid & 3;
    const int wn = wid >> 2;
    const int bm = blockIdx.y * 128;
    const int bn = blockIdx.x * 128;

    const int r0 = tid >> 2;
    const int sg = tid & 3;
    const __nv_bfloat16* Ag = A + (size_t)(bm + r0) * K + sg * 8;
    const __nv_bfloat16* Bg = Bw + (size_t)(bn + r0) * K + sg * 8;
    const uint32_t ldOff = (uint32_t)(r0 * 80 + sg * 16);
    const size_t rowK64 = (size_t)64 * K;

    const int l15 = lane & 15;
    const uint32_t aOff = (uint32_t)((wm * 32 + l15) * 80 + (lane >> 4) * 16);
    const int bnl = (lane & 7) + ((lane >> 4) & 1) * 8;
    const uint32_t bOff = 10240u + (uint32_t)((wn * 64 + bnl) * 80 + ((lane >> 3) & 1) * 16);

    float acc[2][8][4];
    #pragma unroll
    for (int mf = 0; mf < 2; mf++)
        #pragma unroll
        for (int nf = 0; nf < 8; nf++)
            #pragma unroll
            for (int j = 0; j < 4; j++)
                acc[mf][nf][j] = 0.0f;

    const int nch = K / 32;

    auto load_chunk = [&](int s, int ch) {
        const uint32_t stg = smb + (uint32_t)s * GSTAGE;
        const __nv_bfloat16* Ac = Ag + (size_t)ch * 32;
        const __nv_bfloat16* Bc = Bg + (size_t)ch * 32;
        cp16(stg + ldOff, Ac);
        cp16(stg + ldOff + 64 * 80, Ac + rowK64);
        cp16(stg + 10240 + ldOff, Bc);
        cp16(stg + 10240 + ldOff + 64 * 80, Bc + rowK64);
    };

    #pragma unroll
    for (int p = 0; p < 2; ++p) {
        load_chunk(p, p);
        asm volatile("cp.async.commit_group;" ::: "memory");
    }

    int sl = 2;   // stage to fill next
    #pragma unroll 1
    for (int c = 0; c < nch; ++c) {
        asm volatile("cp.async.wait_group 1;" ::: "memory");
        __syncthreads();

        if (c + 2 < nch) load_chunk(sl, c + 2);
        asm volatile("cp.async.commit_group;" ::: "memory");
        sl = (sl == 2) ? 0 : sl + 1;

        const uint32_t so = smb + (uint32_t)((c % 3)) * GSTAGE;
        const uint32_t aA = so + aOff;
        const uint32_t bA = so + bOff;

        #pragma unroll
        for (int ks = 0; ks < 2; ++ks) {
            uint32_t afr[2][4];
            ldsm_x4(afr[0], aA + ks * 32);
            ldsm_x4(afr[1], aA + 16 * 80 + ks * 32);
            uint32_t bfr[4][4];
            #pragma unroll
            for (int nq = 0; nq < 4; ++nq)
                ldsm_x4(bfr[nq], bA + nq * 16 * 80 + ks * 32);

            #pragma unroll
            for (int mf = 0; mf < 2; ++mf)
                #pragma unroll
                for (int nf = 0; nf < 8; ++nf)
                    mma_bf16(acc[mf][nf], afr[mf], &bfr[nf >> 1][(nf & 1) * 2]);
        }
    }

    __syncthreads();

    const int erow = lane >> 2;
    const int ecol = (lane & 3) * 2;
    #pragma unroll
    for (int mf = 0; mf < 2; ++mf) {
        const int row = bm + wm * 32 + mf * 16 + erow;
        #pragma unroll
        for (int nf = 0; nf < 8; ++nf) {
            const int col = bn + wn * 64 + nf * 8 + ecol;
            float2 bb = *(const float2*)(bias + col);
            float2 o0, o1;
            o0.x = acc[mf][nf][0] + bb.x;
            o0.y = acc[mf][nf][1] + bb.y;
            o1.x = acc[mf][nf][2] + bb.x;
            o1.y = acc[mf][nf][3] + bb.y;
            *(float2*)(C + (size_t)row * N + col) = o0;
            *(float2*)(C + (size_t)(row + 8) * N + col) = o1;
        }
    }
}

// ---------------------------------------------------------------------------
// Phase A: local state scan over segment p (no q, no y). Stores F_p.
// grid (4, 64, 3): rowblk, bh, segment. block 128 = 16 rows x 64 cols.
// smem: k 2x16KB, v 2x4KB = 40KB.
// ---------------------------------------------------------------------------
#define TCHA 64
#define PHA_SMEM 40960

__global__ __launch_bounds__(128) void stp_phaseA(
    const float* __restrict__ Lam,
    const float* __restrict__ Gam)
{
    extern __shared__ __align__(16) float sma[];
    const uint32_t smb = smem_u32(sma);

    const int p = blockIdx.z;            // segment 0..2
    const int bh = blockIdx.y;
    const int b = bh >> 4;
    const int h = bh & 15;
    const int tid = threadIdx.x;
    const int w = tid >> 5;
    const int lane = tid & 31;
    const int rg = lane >> 3;
    const int cg = lane & 7;
    const int row0 = blockIdx.x << 4;
    const int rloc = (w << 2) + rg;
    const int i = row0 + rloc;
    const int j0 = cg << 3;

    uint64_t S2[4], r2[4], g2[4];
    {
        const int pbase = (h * Nd + i) * Nd + j0;
        float lv[8], gv[8];
        *(float4*)(lv)     = *(const float4*)(Lam + pbase);
        *(float4*)(lv + 4) = *(const float4*)(Lam + pbase + 4);
        *(float4*)(gv)     = *(const float4*)(Gam + pbase);
        *(float4*)(gv + 4) = *(const float4*)(Gam + pbase + 4);
        float rr[8], gg[8];
        #pragma unroll
        for (int jj = 0; jj < 8; jj++) {
            float sgm = 1.0f / (1.0f + __expf(-lv[jj]));
            rr[jj] = 1.0f - sgm;
            gg[jj] = gv[jj] * 0.125f;
        }
        #pragma unroll
        for (int q = 0; q < 4; q++) {
            r2[q] = pack2(rr[2 * q], rr[2 * q + 1]);
            g2[q] = pack2(gg[2 * q], gg[2 * q + 1]);
            S2[q] = 0ull;
        }
    }

    const float* gq = g_qkv + (size_t)b * NL * 3 * ND + h * Nd;
    const int tseg = p * SEG;

    auto load_chunk = [&](int s, int t0) {
        const uint32_t kb = smb + (uint32_t)s * 16384u;
        const uint32_t vb = smb + 32768u + (uint32_t)s * 4096u;
        #pragma unroll
        for (int it = 0; it < 8; ++it) {
            int idx = tid + (it << 7);
            int st = idx >> 4;
            int seg = (idx & 15) << 2;
            const float* src = gq + (size_t)(t0 + st) * (3 * ND) + ND + seg;
            cp16(kb + ((uint32_t)((st << 6) + seg) << 2), src);
        }
        #pragma unroll
        for (int it = 0; it < 2; ++it) {
            int idx = tid + (it << 7);
            int st = idx >> 2;
            int sg4 = (idx & 3) << 2;
            const float* src = gq + (size_t)(t0 + st) * (3 * ND) + 2 * ND + row0 + sg4;
            cp16(vb + ((uint32_t)((st << 4) + sg4) << 2), src);
        }
        asm volatile("cp.async.commit_group;" ::: "memory");
    };

    load_chunk(0, tseg);

    const int NCA = SEG / TCHA;   // 16
    #pragma unroll 1
    for (int c = 0; c < NCA; ++c) {
        if (c + 1 < NCA) {
            load_chunk((c + 1) & 1, tseg + (c + 1) * TCHA);
            asm volatile("cp.async.wait_group 1;" ::: "memory");
        } else {
            asm volatile("cp.async.wait_group 0;" ::: "memory");
        }
        __syncthreads();

        const int s = c & 1;
        const float* ks = sma + s * 4096;
        const float* vs = sma + 8192 + s * 1024;

        #pragma unroll 4
        for (int tt = 0; tt < TCHA; ++tt) {
            const ulonglong2 kA = *(const ulonglong2*)(ks + (tt << 6) + j0);
            const ulonglong2 kB = *(const ulonglong2*)(ks + (tt << 6) + j0 + 4);
            const float cv = vs[(tt << 4) + rloc];
            const uint64_t v2 = pack2(cv, cv);
            const uint64_t k2[4] = {kA.x, kA.y, kB.x, kB.y};
            #pragma unroll
            for (int q = 0; q < 4; ++q) {
                uint64_t vk = mul2(v2, k2[q]);
                S2[q] = fma2(r2[q], S2[q], mul2(g2[q], vk));
            }
        }
        __syncthreads();
    }

    float* F = g_fst + ((size_t)p * 64 + bh) * 4096 + i * 64 + j0;
    float f[8];
    #pragma unroll
    for (int q = 0; q < 4; ++q) unpack2(f[2 * q], f[2 * q + 1], S2[q]);
    *(float4*)(F)     = *(float4*)(f);
    *(float4*)(F + 4) = *(float4*)(f + 4);
}

// ---------------------------------------------------------------------------
// Phase B: full scan of segment p with true initial state.
// grid (4, 64, 4). smem: q 2x8KB, k 2x8KB, v 2x2KB = 36KB.
// ---------------------------------------------------------------------------
#define TCHB 32
#define PHB_SMEM 36864

__global__ __launch_bounds__(128) void stp_phaseB(
    const float* __restrict__ Wst,
    const float* __restrict__ Lam,
    const float* __restrict__ Gam)
{
    extern __shared__ __align__(16) float smf[];
    const uint32_t smb = smem_u32(smf);

    const int p = blockIdx.z;            // segment 0..3
    const int bh = blockIdx.y;
    const int b = bh >> 4;
    const int h = bh & 15;
    const int tid = threadIdx.x;
    const int w = tid >> 5;
    const int lane = tid & 31;
    const int rg = lane >> 3;
    const int cg = lane & 7;
    const int row0 = blockIdx.x << 4;
    const int rloc = (w << 2) + rg;
    const int i = row0 + rloc;
    const int j0 = cg << 3;

    uint64_t u2[4], r2[4], g2[4], cw2[4];
    {
        const int pbase = (h * Nd + i) * Nd + j0;
        float wv[8], lv[8], gv[8];
        *(float4*)(wv)     = *(const float4*)(Wst + pbase);
        *(float4*)(wv + 4) = *(const float4*)(Wst + pbase + 4);
        *(float4*)(lv)     = *(const float4*)(Lam + pbase);
        *(float4*)(lv + 4) = *(const float4*)(Lam + pbase + 4);
        *(float4*)(gv)     = *(const float4*)(Gam + pbase);
        *(float4*)(gv + 4) = *(const float4*)(Gam + pbase + 4);
        float rr[8], gg[8], cc[8];
        #pragma unroll
        for (int jj = 0; jj < 8; jj++) {
            float sgm = 1.0f / (1.0f + __expf(-lv[jj]));
            rr[jj] = 1.0f - sgm;
            cc[jj] = sgm * wv[jj];
            gg[jj] = gv[jj] * 0.125f;
        }

        // true initial state U_p from phase-A partial states
        float U[8] = {0, 0, 0, 0, 0, 0, 0, 0};
        if (p > 0) {
            float rT[8];
            #pragma unroll
            for (int jj = 0; jj < 8; jj++) {
                float rp = rr[jj];
                #pragma unroll
                for (int q = 0; q < 10; q++) rp *= rp;   // r^1024
                rT[jj] = rp;
            }
            const size_t fo = (size_t)i * 64 + j0;
            {
                const float* F = g_fst + ((size_t)(p - 1) * 64 + bh) * 4096 + fo;
                float f[8];
                *(float4*)(f)     = *(const float4*)(F);
                *(float4*)(f + 4) = *(const float4*)(F + 4);
                #pragma unroll
                for (int jj = 0; jj < 8; jj++) U[jj] += f[jj];
            }
            if (p > 1) {
                const float* F = g_fst + ((size_t)(p - 2) * 64 + bh) * 4096 + fo;
                float f[8];
                *(float4*)(f)     = *(const float4*)(F);
                *(float4*)(f + 4) = *(const float4*)(F + 4);
                #pragma unroll
                for (int jj = 0; jj < 8; jj++) U[jj] += rT[jj] * f[jj];
            }
            if (p > 2) {
                const float* F = g_fst + ((size_t)(p - 3) * 64 + bh) * 4096 + fo;
                float f[8];
                *(float4*)(f)     = *(const float4*)(F);
                *(float4*)(f + 4) = *(const float4*)(F + 4);
                #pragma unroll
                for (int jj = 0; jj < 8; jj++) U[jj] += rT[jj] * rT[jj] * f[jj];
            }
        }

        #pragma unroll
        for (int q = 0; q < 4; q++) {
            u2[q]  = pack2(wv[2 * q] + U[2 * q], wv[2 * q + 1] + U[2 * q + 1]);
            r2[q]  = pack2(rr[2 * q], rr[2 * q + 1]);
            g2[q]  = pack2(gg[2 * q], gg[2 * q + 1]);
            cw2[q] = pack2(cc[2 * q], cc[2 * q + 1]);
        }
    }

    const float* gq = g_qkv + (size_t)b * NL * 3 * ND + h * Nd;
    float* yout = g_y + (size_t)b * NL * ND + h * Nd + i;
    const int tseg = p * SEG;

    auto load_chunk = [&](int s, int t0) {
        const uint32_t qb = smb + (uint32_t)s * 8192u;
        const uint32_t kb = smb + 16384u + (uint32_t)s * 8192u;
        const uint32_t vb = smb + 32768u + (uint32_t)s * 2048u;
        #pragma unroll
        for (int it = 0; it < 4; ++it) {
            int idx = tid + (it << 7);
            int st = idx >> 4;
            int seg = (idx & 15) << 2;
            const float* src = gq + (size_t)(t0 + st) * (3 * ND) + seg;
            uint32_t o = (uint32_t)((st << 6) + seg) << 2;
            cp16(qb + o, src);
            cp16(kb + o, src + ND);
        }
        {
            int st = tid >> 2;
            int sg4 = (tid & 3) << 2;
            const float* src = gq + (size_t)(t0 + st) * (3 * ND) + 2 * ND + row0 + sg4;
            cp16(vb + ((uint32_t)((st << 4) + sg4) << 2), src);
        }
        asm volatile("cp.async.commit_group;" ::: "memory");
    };

    load_chunk(0, tseg);

    const int NCB = SEG / TCHB;   // 32
    #pragma unroll 1
    for (int c = 0; c < NCB; ++c) {
        if (c + 1 < NCB) {
            load_chunk((c + 1) & 1, tseg + (c + 1) * TCHB);
            asm volatile("cp.async.wait_group 1;" ::: "memory");
        } else {
            asm volatile("cp.async.wait_group 0;" ::: "memory");
        }
        __syncthreads();

        const int s = c & 1;
        const float* qs = smf + s * 2048;
        const float* ks = smf + 4096 + s * 2048;
        const float* vs = smf + 8192 + s * 512;

        #pragma unroll 1
        for (int tt0 = 0; tt0 < TCHB; tt0 += 8) {
            float yps[8];
            #pragma unroll
            for (int ss = 0; ss < 8; ++ss) {
                const int tt = tt0 + ss;
                const ulonglong2 qA = *(const ulonglong2*)(qs + (tt << 6) + j0);
                const ulonglong2 qB = *(const ulonglong2*)(qs + (tt << 6) + j0 + 4);
                const ulonglong2 kA = *(const ulonglong2*)(ks + (tt << 6) + j0);
                const ulonglong2 kB = *(const ulonglong2*)(ks + (tt << 6) + j0 + 4);
                const float cv = vs[(tt << 4) + rloc];
                const uint64_t v2 = pack2(cv, cv);
                const uint64_t q2[4] = {qA.x, qA.y, qB.x, qB.y};
                const uint64_t k2[4] = {kA.x, kA.y, kB.x, kB.y};

                uint64_t acc = 0ull;
                #pragma unroll
                for (int q = 0; q < 4; ++q) {
                    uint64_t vk = mul2(v2, k2[q]);
                    uint64_t tmp = fma2(g2[q], vk, cw2[q]);
                    u2[q] = fma2(r2[q], u2[q], tmp);
                    acc = fma2(u2[q], q2[q], acc);
                }
                yps[ss] = hadd2(acc);
            }

            #pragma unroll
            for (int ss = 0; ss < 8; ++ss) yps[ss] += __shfl_xor_sync(0xffffffffu, yps[ss], 1);
            #pragma unroll
            for (int ss = 0; ss < 8; ++ss) yps[ss] += __shfl_xor_sync(0xffffffffu, yps[ss], 2);
            #pragma unroll
            for (int ss = 0; ss < 8; ++ss) yps[ss] += __shfl_xor_sync(0xffffffffu, yps[ss], 4);

            if (cg == 0) {
                const size_t t0g = (size_t)tseg + c * TCHB + tt0;
                #pragma unroll
                for (int ss = 0; ss < 8; ++ss)
                    yout[(t0g + ss) * ND] = yps[ss];
            }
        }
        __syncthreads();
    }
}

// ---------------------------------------------------------------------------

extern "C" void kernel_launch(void* const* d_in, const int* in_sizes, int n_in,
                              void* d_out, int out_size)
{
    const float* x          = (const float*)d_in[0];
    const float* Wqkv_w     = (const float*)d_in[1];
    const float* Wqkv_b     = (const float*)d_in[2];
    const float* out_w      = (const float*)d_in[3];
    const float* out_b      = (const float*)d_in[4];
    const float* W_static   = (const float*)d_in[5];
    const float* Lambda_raw = (const float*)d_in[6];
    const float* Gamma      = (const float*)d_in[7];

    float* qkv = nullptr;
    float* y = nullptr;
    __nv_bfloat16 *sA = nullptr, *sB1 = nullptr, *sB2 = nullptr;
    cudaGetSymbolAddress((void**)&qkv, g_qkv);
    cudaGetSymbolAddress((void**)&y, g_y);
    cudaGetSymbolAddress((void**)&sA, g_sA);
    cudaGetSymbolAddress((void**)&sB1, g_sB1);
    cudaGetSymbolAddress((void**)&sB2, g_sB2);

    static bool attr_set = false;
    if (!attr_set) {
        cudaFuncSetAttribute(gemm_mma, cudaFuncAttributeMaxDynamicSharedMemorySize, GEMM_SMEM);
        cudaFuncSetAttribute(stp_phaseA, cudaFuncAttributeMaxDynamicSharedMemorySize, PHA_SMEM);
        cudaFuncSetAttribute(stp_phaseB, cudaFuncAttributeMaxDynamicSharedMemorySize, PHB_SMEM);
        attr_set = true;
    }

    const long nx = (long)MTOT * ND;
    const long nw1 = (long)3 * ND * ND;
    const long nw2 = (long)ND * ND;

    split3_kernel<<<(unsigned)((nx / 4 + 255) / 256), 256>>>(x, sA, ND, nx, 0);
    split3_kernel<<<(unsigned)((nw1 / 4 + 255) / 256), 256>>>(Wqkv_w, sB1, ND, nw1, 1);
    gemm_mma<<<dim3(3 * ND / 128, MTOT / 128), 256, GEMM_SMEM>>>(sA, sB1, Wqkv_b, qkv, 3 * ND, K3);

    // segmented scan: phase A (local states) then phase B (true scan + y)
    stp_phaseA<<<dim3(4, NB * NH, 3), 128, PHA_SMEM>>>(Lambda_raw, Gamma);
    stp_phaseB<<<dim3(4, NB * NH, 4), 128, PHB_SMEM>>>(W_static, Lambda_raw, Gamma);

    split3_kernel<<<(unsigned)((nx / 4 + 255) / 256), 256>>>(y, sA, ND, nx, 0);
    split3_kernel<<<(unsigned)((nw2 / 4 + 255) / 256), 256>>>(out_w, sB2, ND, nw2, 1);
    gemm_mma<<<dim3(ND / 128, MTOT / 128), 256, GEMM_SMEM>>>(sA, sB2, out_b, (float*)d_out, ND, K3);
}

// round 7
// speedup vs baseline: 3.5070x; 1.2605x over previous
#include <cuda_runtime.h>
#include <cuda_fp16.h>
#include <cstdint>

#define NB 4
#define NL 4096
#define NH 16
#define ND 1024
#define Nd 64
#define MTOT (NB * NL)          // 16384
#define K2 2048                 // 2 * 1024 (split-fp16 extended K)
#define SEGB 512                // phase-B segment length
#define SUBA 256                // phase-A sub-segment length
#define NSUBA 14                // sub-segments covering [0, 3584)

// ---------------------------------------------------------------------------
// Device-global scratch (no allocations allowed)
// ---------------------------------------------------------------------------
__device__ float g_qkv[(size_t)NB * NL * 3 * ND];
__device__ float g_fst[(size_t)NSUBA * 64 * 4096];   // sub-segment local states
__device__ float g_ust[(size_t)8 * 64 * 4096];       // segment-init states
__device__ __half g_sA[(size_t)MTOT * K2];           // split A (x, then y)
__device__ __half g_sB1[(size_t)3 * ND * K2];        // split Wqkv_w
__device__ __half g_sB2[(size_t)ND * K2];            // split out_w

// ---------------------------------------------------------------------------
__device__ __forceinline__ uint32_t smem_u32(const void* p) {
    uint32_t a;
    asm("{ .reg .u64 t; cvta.to.shared.u64 t, %1; cvt.u32.u64 %0, t; }"
        : "=r"(a) : "l"(p));
    return a;
}
__device__ __forceinline__ void ldsm_x4(uint32_t* r, uint32_t addr) {
    asm volatile("ldmatrix.sync.aligned.m8n8.x4.shared.b16 {%0,%1,%2,%3}, [%4];"
                 : "=r"(r[0]), "=r"(r[1]), "=r"(r[2]), "=r"(r[3]) : "r"(addr));
}
__device__ __forceinline__ void mma_f16(float* d, const uint32_t* a, const uint32_t* b) {
    asm volatile(
        "mma.sync.aligned.m16n8k16.row.col.f32.f16.f16.f32 "
        "{%0,%1,%2,%3}, {%4,%5,%6,%7}, {%8,%9}, {%0,%1,%2,%3};"
        : "+f"(d[0]), "+f"(d[1]), "+f"(d[2]), "+f"(d[3])
        : "r"(a[0]), "r"(a[1]), "r"(a[2]), "r"(a[3]), "r"(b[0]), "r"(b[1]));
}
__device__ __forceinline__ void cp16(uint32_t saddr, const void* gaddr) {
    asm volatile("cp.async.cg.shared.global [%0], [%1], 16;" :: "r"(saddr), "l"(gaddr));
}
__device__ __forceinline__ uint64_t mul2(uint64_t a, uint64_t b) {
    uint64_t d; asm("mul.rn.f32x2 %0, %1, %2;" : "=l"(d) : "l"(a), "l"(b)); return d;
}
__device__ __forceinline__ uint64_t fma2(uint64_t a, uint64_t b, uint64_t c) {
    uint64_t d; asm("fma.rn.f32x2 %0, %1, %2, %3;" : "=l"(d) : "l"(a), "l"(b), "l"(c)); return d;
}
__device__ __forceinline__ uint64_t pack2(float lo, float hi) {
    uint64_t d;
    asm("mov.b64 %0, {%1, %2};" : "=l"(d) : "r"(__float_as_uint(lo)), "r"(__float_as_uint(hi)));
    return d;
}
__device__ __forceinline__ float hadd2(uint64_t v) {
    uint32_t lo, hi;
    asm("mov.b64 {%0, %1}, %2;" : "=r"(lo), "=r"(hi) : "l"(v));
    return __uint_as_float(lo) + __uint_as_float(hi);
}
__device__ __forceinline__ void unpack2(float& lo, float& hi, uint64_t v) {
    uint32_t l, h;
    asm("mov.b64 {%0, %1}, %2;" : "=r"(l), "=r"(h) : "l"(v));
    lo = __uint_as_float(l); hi = __uint_as_float(h);
}

// ---------------------------------------------------------------------------
// Split-fp16 conversion: src (R,K) f32 -> dst (R,2K) fp16.
//   A-side (bside=0): [hi | lo];  B-side (bside=1): [hi | hi]
// ---------------------------------------------------------------------------
__global__ __launch_bounds__(256) void split2_kernel(
    const float* __restrict__ src, __half* __restrict__ dst,
    int K, long total, int bside)
{
    long i = ((long)blockIdx.x * blockDim.x + threadIdx.x) * 4;
    if (i >= total) return;
    float4 v = *(const float4*)(src + i);
    int r = (int)(i / K);
    int k = (int)(i - (long)r * K);
    float vv[4] = {v.x, v.y, v.z, v.w};
    __half hi[4], lo[4];
    #pragma unroll
    for (int j = 0; j < 4; j++) {
        hi[j] = __float2half_rn(vv[j]);
        lo[j] = __float2half_rn(vv[j] - __half2float(hi[j]));
    }
    __half2 h01, h23, l01, l23;
    h01.x = hi[0]; h01.y = hi[1]; h23.x = hi[2]; h23.y = hi[3];
    l01.x = lo[0]; l01.y = lo[1]; l23.x = lo[2]; l23.y = lo[3];

    __half* d0 = dst + (size_t)r * (2 * K) + k;
    *(__half2*)(d0)     = h01;
    *(__half2*)(d0 + 2) = h23;
    if (bside == 0) {
        *(__half2*)(d0 + K)     = l01;
        *(__half2*)(d0 + K + 2) = l23;
    } else {
        *(__half2*)(d0 + K)     = h01;
        *(__half2*)(d0 + K + 2) = h23;
    }
}

// ---------------------------------------------------------------------------
// mma.sync fp16 GEMM: C[m,n] = sum_k A[m,k]*Bw[n,k] + bias[n]
// 128x128 CTA tile, BK=32, 3-stage cp.async, 60KB smem, 2 CTAs/SM.
// ---------------------------------------------------------------------------
#define GSTAGE 20480
#define GEMM_SMEM (3 * GSTAGE)

__global__ __launch_bounds__(256, 2) void gemm_mma(
    const __half* __restrict__ A, const __half* __restrict__ Bw,
    const float* __restrict__ bias, float* __restrict__ C,
    int N, int K)
{
    extern __shared__ __align__(16) char dsm[];
    const uint32_t smb = smem_u32(dsm);

    const int tid = threadIdx.x;
    const int wid = tid >> 5;
    const int lane = tid & 31;
    const int wm = wid & 3;
    const int wn = wid >> 2;
    const int bm = blockIdx.y * 128;
    const int bn = blockIdx.x * 128;

    const int r0 = tid >> 2;
    const int sg = tid & 3;
    const __half* Ag = A + (size_t)(bm + r0) * K + sg * 8;
    const __half* Bg = Bw + (size_t)(bn + r0) * K + sg * 8;
    const uint32_t ldOff = (uint32_t)(r0 * 80 + sg * 16);
    const size_t rowK64 = (size_t)64 * K;

    const int l15 = lane & 15;
    const uint32_t aOff = (uint32_t)((wm * 32 + l15) * 80 + (lane >> 4) * 16);
    const int bnl = (lane & 7) + ((lane >> 4) & 1) * 8;
    const uint32_t bOff = 10240u + (uint32_t)((wn * 64 + bnl) * 80 + ((lane >> 3) & 1) * 16);

    float acc[2][8][4];
    #pragma unroll
    for (int mf = 0; mf < 2; mf++)
        #pragma unroll
        for (int nf = 0; nf < 8; nf++)
            #pragma unroll
            for (int j = 0; j < 4; j++)
                acc[mf][nf][j] = 0.0f;

    const int nch = K / 32;

    auto load_chunk = [&](int s, int ch) {
        const uint32_t stg = smb + (uint32_t)s * GSTAGE;
        const __half* Ac = Ag + (size_t)ch * 32;
        const __half* Bc = Bg + (size_t)ch * 32;
        cp16(stg + ldOff, Ac);
        cp16(stg + ldOff + 64 * 80, Ac + rowK64);
        cp16(stg + 10240 + ldOff, Bc);
        cp16(stg + 10240 + ldOff + 64 * 80, Bc + rowK64);
    };

    #pragma unroll
    for (int p = 0; p < 2; ++p) {
        load_chunk(p, p);
        asm volatile("cp.async.commit_group;" ::: "memory");
    }

    int sl = 2;
    #pragma unroll 1
    for (int c = 0; c < nch; ++c) {
        asm volatile("cp.async.wait_group 1;" ::: "memory");
        __syncthreads();

        if (c + 2 < nch) load_chunk(sl, c + 2);
        asm volatile("cp.async.commit_group;" ::: "memory");
        sl = (sl == 2) ? 0 : sl + 1;

        const uint32_t so = smb + (uint32_t)((c % 3)) * GSTAGE;
        const uint32_t aA = so + aOff;
        const uint32_t bA = so + bOff;

        #pragma unroll
        for (int ks = 0; ks < 2; ++ks) {
            uint32_t afr[2][4];
            ldsm_x4(afr[0], aA + ks * 32);
            ldsm_x4(afr[1], aA + 16 * 80 + ks * 32);
            uint32_t bfr[4][4];
            #pragma unroll
            for (int nq = 0; nq < 4; ++nq)
                ldsm_x4(bfr[nq], bA + nq * 16 * 80 + ks * 32);

            #pragma unroll
            for (int mf = 0; mf < 2; ++mf)
                #pragma unroll
                for (int nf = 0; nf < 8; ++nf)
                    mma_f16(acc[mf][nf], afr[mf], &bfr[nf >> 1][(nf & 1) * 2]);
        }
    }

    __syncthreads();

    const int erow = lane >> 2;
    const int ecol = (lane & 3) * 2;
    #pragma unroll
    for (int mf = 0; mf < 2; ++mf) {
        const int row = bm + wm * 32 + mf * 16 + erow;
        #pragma unroll
        for (int nf = 0; nf < 8; ++nf) {
            const int col = bn + wn * 64 + nf * 8 + ecol;
            float2 bb = *(const float2*)(bias + col);
            float2 o0, o1;
            o0.x = acc[mf][nf][0] + bb.x;
            o0.y = acc[mf][nf][1] + bb.y;
            o1.x = acc[mf][nf][2] + bb.x;
            o1.y = acc[mf][nf][3] + bb.y;
            *(float2*)(C + (size_t)row * N + col) = o0;
            *(float2*)(C + (size_t)(row + 8) * N + col) = o1;
        }
    }
}

// ---------------------------------------------------------------------------
// Phase A: local state over sub-segment m (256 steps, k/v only).
// grid (4, 64, 14). smem: k 2x16KB, v 2x4KB = 40KB.
// ---------------------------------------------------------------------------
#define TCHA 64
#define PHA_SMEM 40960

__global__ __launch_bounds__(128) void stp_phaseA(
    const float* __restrict__ Lam,
    const float* __restrict__ Gam)
{
    extern __shared__ __align__(16) float sma[];
    const uint32_t smb = smem_u32(sma);

    const int m = blockIdx.z;            // sub-segment 0..13
    const int bh = blockIdx.y;
    const int b = bh >> 4;
    const int h = bh & 15;
    const int tid = threadIdx.x;
    const int w = tid >> 5;
    const int lane = tid & 31;
    const int rg = lane >> 3;
    const int cg = lane & 7;
    const int row0 = blockIdx.x << 4;
    const int rloc = (w << 2) + rg;
    const int i = row0 + rloc;
    const int j0 = cg << 3;

    uint64_t S2[4], r2[4], g2[4];
    {
        const int pbase = (h * Nd + i) * Nd + j0;
        float lv[8], gv[8];
        *(float4*)(lv)     = *(const float4*)(Lam + pbase);
        *(float4*)(lv + 4) = *(const float4*)(Lam + pbase + 4);
        *(float4*)(gv)     = *(const float4*)(Gam + pbase);
        *(float4*)(gv + 4) = *(const float4*)(Gam + pbase + 4);
        float rr[8], gg[8];
        #pragma unroll
        for (int jj = 0; jj < 8; jj++) {
            float sgm = 1.0f / (1.0f + __expf(-lv[jj]));
            rr[jj] = 1.0f - sgm;
            gg[jj] = gv[jj] * 0.125f;
        }
        #pragma unroll
        for (int q = 0; q < 4; q++) {
            r2[q] = pack2(rr[2 * q], rr[2 * q + 1]);
            g2[q] = pack2(gg[2 * q], gg[2 * q + 1]);
            S2[q] = 0ull;
        }
    }

    const float* gq = g_qkv + (size_t)b * NL * 3 * ND + h * Nd;
    const int tseg = m * SUBA;

    auto load_chunk = [&](int s, int t0) {
        const uint32_t kb = smb + (uint32_t)s * 16384u;
        const uint32_t vb = smb + 32768u + (uint32_t)s * 4096u;
        #pragma unroll
        for (int it = 0; it < 8; ++it) {
            int idx = tid + (it << 7);
            int st = idx >> 4;
            int seg = (idx & 15) << 2;
            const float* src = gq + (size_t)(t0 + st) * (3 * ND) + ND + seg;
            cp16(kb + ((uint32_t)((st << 6) + seg) << 2), src);
        }
        #pragma unroll
        for (int it = 0; it < 2; ++it) {
            int idx = tid + (it << 7);
            int st = idx >> 2;
            int sg4 = (idx & 3) << 2;
            const float* src = gq + (size_t)(t0 + st) * (3 * ND) + 2 * ND + row0 + sg4;
            cp16(vb + ((uint32_t)((st << 4) + sg4) << 2), src);
        }
        asm volatile("cp.async.commit_group;" ::: "memory");
    };

    load_chunk(0, tseg);

    const int NCA = SUBA / TCHA;   // 4
    #pragma unroll 1
    for (int c = 0; c < NCA; ++c) {
        if (c + 1 < NCA) {
            load_chunk((c + 1) & 1, tseg + (c + 1) * TCHA);
            asm volatile("cp.async.wait_group 1;" ::: "memory");
        } else {
            asm volatile("cp.async.wait_group 0;" ::: "memory");
        }
        __syncthreads();

        const int s = c & 1;
        const float* ks = sma + s * 4096;
        const float* vs = sma + 8192 + s * 1024;

        #pragma unroll 4
        for (int tt = 0; tt < TCHA; ++tt) {
            const ulonglong2 kA = *(const ulonglong2*)(ks + (tt << 6) + j0);
            const ulonglong2 kB = *(const ulonglong2*)(ks + (tt << 6) + j0 + 4);
            const float cv = vs[(tt << 4) + rloc];
            const uint64_t v2 = pack2(cv, cv);
            const uint64_t k2[4] = {kA.x, kA.y, kB.x, kB.y};
            #pragma unroll
            for (int q = 0; q < 4; ++q) {
                uint64_t vk = mul2(v2, k2[q]);
                S2[q] = fma2(r2[q], S2[q], mul2(g2[q], vk));
            }
        }
        __syncthreads();
    }

    float* F = g_fst + ((size_t)m * 64 + bh) * 4096 + i * 64 + j0;
    float f[8];
    #pragma unroll
    for (int q = 0; q < 4; ++q) unpack2(f[2 * q], f[2 * q + 1], S2[q]);
    *(float4*)(F)     = *(float4*)(f);
    *(float4*)(F + 4) = *(float4*)(f + 4);
}

// ---------------------------------------------------------------------------
// Combine: Horner over 14 sub-segment states -> segment-init states U_s
// (s = 1..7, stride r^256 per sub-segment). One thread per (bh, elem).
// ---------------------------------------------------------------------------
__global__ __launch_bounds__(256) void stp_combine(const float* __restrict__ Lam)
{
    const int e = blockIdx.x * 256 + threadIdx.x;   // 0..262143
    const int bh = e >> 12;
    const int idx = e & 4095;
    const int h = bh & 15;

    const float lam = Lam[h * 4096 + idx];
    const float sgm = 1.0f / (1.0f + __expf(-lam));
    float r = 1.0f - sgm;
    float r256 = r;
    #pragma unroll
    for (int q = 0; q < 8; q++) r256 *= r256;   // r^256

    float U = 0.0f;
    #pragma unroll
    for (int m = 0; m < NSUBA; ++m) {
        if (m > 0 && (m & 1) == 0)
            g_ust[((size_t)(m >> 1) * 64 + bh) * 4096 + idx] = U;
        U = r256 * U + g_fst[((size_t)m * 64 + bh) * 4096 + idx];
    }
    g_ust[((size_t)7 * 64 + bh) * 4096 + idx] = U;
}

// ---------------------------------------------------------------------------
// Phase B: full scan of segment p (512 steps) with true initial state.
// grid (4, 64, 8). smem 36KB. Writes y directly as split-fp16 into g_sA.
// ---------------------------------------------------------------------------
#define TCHB 32
#define PHB_SMEM 36864

__global__ __launch_bounds__(128) void stp_phaseB(
    const float* __restrict__ Wst,
    const float* __restrict__ Lam,
    const float* __restrict__ Gam)
{
    extern __shared__ __align__(16) float smf[];
    const uint32_t smb = smem_u32(smf);

    const int p = blockIdx.z;            // segment 0..7
    const int bh = blockIdx.y;
    const int b = bh >> 4;
    const int h = bh & 15;
    const int tid = threadIdx.x;
    const int w = tid >> 5;
    const int lane = tid & 31;
    const int rg = lane >> 3;
    const int cg = lane & 7;
    const int row0 = blockIdx.x << 4;
    const int rloc = (w << 2) + rg;
    const int i = row0 + rloc;
    const int j0 = cg << 3;

    uint64_t u2[4], r2[4], g2[4], cw2[4];
    {
        const int pbase = (h * Nd + i) * Nd + j0;
        float wv[8], lv[8], gv[8];
        *(float4*)(wv)     = *(const float4*)(Wst + pbase);
        *(float4*)(wv + 4) = *(const float4*)(Wst + pbase + 4);
        *(float4*)(lv)     = *(const float4*)(Lam + pbase);
        *(float4*)(lv + 4) = *(const float4*)(Lam + pbase + 4);
        *(float4*)(gv)     = *(const float4*)(Gam + pbase);
        *(float4*)(gv + 4) = *(const float4*)(Gam + pbase + 4);
        float rr[8], gg[8], cc[8];
        #pragma unroll
        for (int jj = 0; jj < 8; jj++) {
            float sgm = 1.0f / (1.0f + __expf(-lv[jj]));
            rr[jj] = 1.0f - sgm;
            cc[jj] = sgm * wv[jj];
            gg[jj] = gv[jj] * 0.125f;
        }

        float U[8] = {0, 0, 0, 0, 0, 0, 0, 0};
        if (p > 0) {
            const float* Up = g_ust + ((size_t)p * 64 + bh) * 4096 + i * 64 + j0;
            *(float4*)(U)     = *(const float4*)(Up);
            *(float4*)(U + 4) = *(const float4*)(Up + 4);
        }

        #pragma unroll
        for (int q = 0; q < 4; q++) {
            u2[q]  = pack2(wv[2 * q] + U[2 * q], wv[2 * q + 1] + U[2 * q + 1]);
            r2[q]  = pack2(rr[2 * q], rr[2 * q + 1]);
            g2[q]  = pack2(gg[2 * q], gg[2 * q + 1]);
            cw2[q] = pack2(cc[2 * q], cc[2 * q + 1]);
        }
    }

    const float* gq = g_qkv + (size_t)b * NL * 3 * ND + h * Nd;
    // split-fp16 y destination: row = b*NL + t, col = h*64 + i
    __half* ybase = g_sA + (size_t)(b * NL) * K2 + (h * 64 + i);
    const int tseg = p * SEGB;

    auto load_chunk = [&](int s, int t0) {
        const uint32_t qb = smb + (uint32_t)s * 8192u;
        const uint32_t kb = smb + 16384u + (uint32_t)s * 8192u;
        const uint32_t vb = smb + 32768u + (uint32_t)s * 2048u;
        #pragma unroll
        for (int it = 0; it < 4; ++it) {
            int idx = tid + (it << 7);
            int st = idx >> 4;
            int seg = (idx & 15) << 2;
            const float* src = gq + (size_t)(t0 + st) * (3 * ND) + seg;
            uint32_t o = (uint32_t)((st << 6) + seg) << 2;
            cp16(qb + o, src);
            cp16(kb + o, src + ND);
        }
        {
            int st = tid >> 2;
            int sg4 = (tid & 3) << 2;
            const float* src = gq + (size_t)(t0 + st) * (3 * ND) + 2 * ND + row0 + sg4;
            cp16(vb + ((uint32_t)((st << 4) + sg4) << 2), src);
        }
        asm volatile("cp.async.commit_group;" ::: "memory");
    };

    load_chunk(0, tseg);

    const int NCB = SEGB / TCHB;   // 16
    #pragma unroll 1
    for (int c = 0; c < NCB; ++c) {
        if (c + 1 < NCB) {
            load_chunk((c + 1) & 1, tseg + (c + 1) * TCHB);
            asm volatile("cp.async.wait_group 1;" ::: "memory");
        } else {
            asm volatile("cp.async.wait_group 0;" ::: "memory");
        }
        __syncthreads();

        const int s = c & 1;
        const float* qs = smf + s * 2048;
        const float* ks = smf + 4096 + s * 2048;
        const float* vs = smf + 8192 + s * 512;

        #pragma unroll 1
        for (int tt0 = 0; tt0 < TCHB; tt0 += 8) {
            float yps[8];
            #pragma unroll
            for (int ss = 0; ss < 8; ++ss) {
                const int tt = tt0 + ss;
                const ulonglong2 qA = *(const ulonglong2*)(qs + (tt << 6) + j0);
                const ulonglong2 qB = *(const ulonglong2*)(qs + (tt << 6) + j0 + 4);
                const ulonglong2 kA = *(const ulonglong2*)(ks + (tt << 6) + j0);
                const ulonglong2 kB = *(const ulonglong2*)(ks + (tt << 6) + j0 + 4);
                const float cv = vs[(tt << 4) + rloc];
                const uint64_t v2 = pack2(cv, cv);
                const uint64_t q2[4] = {qA.x, qA.y, qB.x, qB.y};
                const uint64_t k2[4] = {kA.x, kA.y, kB.x, kB.y};

                uint64_t acc = 0ull;
                #pragma unroll
                for (int q = 0; q < 4; ++q) {
                    uint64_t vk = mul2(v2, k2[q]);
                    uint64_t tmp = fma2(g2[q], vk, cw2[q]);
                    u2[q] = fma2(r2[q], u2[q], tmp);
                    acc = fma2(u2[q], q2[q], acc);
                }
                yps[ss] = hadd2(acc);
            }

            #pragma unroll
            for (int ss = 0; ss < 8; ++ss) yps[ss] += __shfl_xor_sync(0xffffffffu, yps[ss], 1);
            #pragma unroll
            for (int ss = 0; ss < 8; ++ss) yps[ss] += __shfl_xor_sync(0xffffffffu, yps[ss], 2);
            #pragma unroll
            for (int ss = 0; ss < 8; ++ss) yps[ss] += __shfl_xor_sync(0xffffffffu, yps[ss], 4);

            if (cg == 0) {
                const size_t t0g = (size_t)tseg + c * TCHB + tt0;
                #pragma unroll
                for (int ss = 0; ss < 8; ++ss) {
                    __half hi = __float2half_rn(yps[ss]);
                    __half lo = __float2half_rn(yps[ss] - __half2float(hi));
                    __half* yp = ybase + (t0g + ss) * K2;
                    yp[0] = hi;
                    yp[ND] = lo;
                }
            }
        }
        __syncthreads();
    }
}

// ---------------------------------------------------------------------------

extern "C" void kernel_launch(void* const* d_in, const int* in_sizes, int n_in,
                              void* d_out, int out_size)
{
    const float* x          = (const float*)d_in[0];
    const float* Wqkv_w     = (const float*)d_in[1];
    const float* Wqkv_b     = (const float*)d_in[2];
    const float* out_w      = (const float*)d_in[3];
    const float* out_b      = (const float*)d_in[4];
    const float* W_static   = (const float*)d_in[5];
    const float* Lambda_raw = (const float*)d_in[6];
    const float* Gamma      = (const float*)d_in[7];

    float* qkv = nullptr;
    __half *sA = nullptr, *sB1 = nullptr, *sB2 = nullptr;
    cudaGetSymbolAddress((void**)&qkv, g_qkv);
    cudaGetSymbolAddress((void**)&sA, g_sA);
    cudaGetSymbolAddress((void**)&sB1, g_sB1);
    cudaGetSymbolAddress((void**)&sB2, g_sB2);

    static bool attr_set = false;
    if (!attr_set) {
        cudaFuncSetAttribute(gemm_mma, cudaFuncAttributeMaxDynamicSharedMemorySize, GEMM_SMEM);
        cudaFuncSetAttribute(stp_phaseA, cudaFuncAttributeMaxDynamicSharedMemorySize, PHA_SMEM);
        cudaFuncSetAttribute(stp_phaseB, cudaFuncAttributeMaxDynamicSharedMemorySize, PHB_SMEM);
        attr_set = true;
    }

    const long nx = (long)MTOT * ND;
    const long nw1 = (long)3 * ND * ND;
    const long nw2 = (long)ND * ND;

    // split x -> sA (A-side), Wqkv_w -> sB1 (B-side)
    split2_kernel<<<(unsigned)((nx / 4 + 255) / 256), 256>>>(x, sA, ND, nx, 0);
    split2_kernel<<<(unsigned)((nw1 / 4 + 255) / 256), 256>>>(Wqkv_w, sB1, ND, nw1, 1);
    // qkv = x @ Wqkv_w^T + b
    gemm_mma<<<dim3(3 * ND / 128, MTOT / 128), 256, GEMM_SMEM>>>(sA, sB1, Wqkv_b, qkv, 3 * ND, K2);

    // segmented scan: phase A -> combine -> phase B (writes split y into sA)
    stp_phaseA<<<dim3(4, NB * NH, NSUBA), 128, PHA_SMEM>>>(Lambda_raw, Gamma);
    stp_combine<<<1024, 256>>>(Lambda_raw);
    stp_phaseB<<<dim3(4, NB * NH, 8), 128, PHB_SMEM>>>(W_static, Lambda_raw, Gamma);

    // split out_w -> sB2 (B-side); out = y @ out_w^T + b
    split2_kernel<<<(unsigned)((nw2 / 4 + 255) / 256), 256>>>(out_w, sB2, ND, nw2, 1);
    gemm_mma<<<dim3(ND / 128, MTOT / 128), 256, GEMM_SMEM>>>(sA, sB2, out_b, (float*)d_out, ND, K2);
}

// round 8
// speedup vs baseline: 4.0766x; 1.1624x over previous
#include <cuda_runtime.h>
#include <cuda_fp16.h>
#include <cstdint>

#define NB 4
#define NL 4096
#define NH 16
#define ND 1024
#define Nd 64
#define MTOT (NB * NL)          // 16384
#define K2 2048                 // 2 * 1024 (split-fp16 extended K)
#define SEGB 512                // phase-B segment length
#define SUBA 256                // phase-A sub-segment length
#define NSUBA 14                // sub-segments covering [0, 3584)

// ---------------------------------------------------------------------------
// Device-global scratch (no allocations allowed)
// ---------------------------------------------------------------------------
__device__ __half g_qkv[(size_t)NB * NL * 3 * ND];   // fp16 qkv (100 MB)
__device__ float g_fst[(size_t)NSUBA * 64 * 4096];   // sub-segment local states
__device__ float g_ust[(size_t)8 * 64 * 4096];       // segment-init states
__device__ __half g_sA[(size_t)MTOT * K2];           // split A (x, then y)
__device__ __half g_sB1[(size_t)3 * ND * K2];        // split Wqkv_w
__device__ __half g_sB2[(size_t)ND * K2];            // split out_w

// ---------------------------------------------------------------------------
__device__ __forceinline__ uint32_t smem_u32(const void* p) {
    uint32_t a;
    asm("{ .reg .u64 t; cvta.to.shared.u64 t, %1; cvt.u32.u64 %0, t; }"
        : "=r"(a) : "l"(p));
    return a;
}
__device__ __forceinline__ void ldsm_x4(uint32_t* r, uint32_t addr) {
    asm volatile("ldmatrix.sync.aligned.m8n8.x4.shared.b16 {%0,%1,%2,%3}, [%4];"
                 : "=r"(r[0]), "=r"(r[1]), "=r"(r[2]), "=r"(r[3]) : "r"(addr));
}
__device__ __forceinline__ void mma_f16(float* d, const uint32_t* a, const uint32_t* b) {
    asm volatile(
        "mma.sync.aligned.m16n8k16.row.col.f32.f16.f16.f32 "
        "{%0,%1,%2,%3}, {%4,%5,%6,%7}, {%8,%9}, {%0,%1,%2,%3};"
        : "+f"(d[0]), "+f"(d[1]), "+f"(d[2]), "+f"(d[3])
        : "r"(a[0]), "r"(a[1]), "r"(a[2]), "r"(a[3]), "r"(b[0]), "r"(b[1]));
}
__device__ __forceinline__ void cp16(uint32_t saddr, const void* gaddr) {
    asm volatile("cp.async.cg.shared.global [%0], [%1], 16;" :: "r"(saddr), "l"(gaddr));
}
__device__ __forceinline__ uint64_t mul2(uint64_t a, uint64_t b) {
    uint64_t d; asm("mul.rn.f32x2 %0, %1, %2;" : "=l"(d) : "l"(a), "l"(b)); return d;
}
__device__ __forceinline__ uint64_t fma2(uint64_t a, uint64_t b, uint64_t c) {
    uint64_t d; asm("fma.rn.f32x2 %0, %1, %2, %3;" : "=l"(d) : "l"(a), "l"(b), "l"(c)); return d;
}
__device__ __forceinline__ uint64_t pack2(float lo, float hi) {
    uint64_t d;
    asm("mov.b64 %0, {%1, %2};" : "=l"(d) : "r"(__float_as_uint(lo)), "r"(__float_as_uint(hi)));
    return d;
}
__device__ __forceinline__ float hadd2(uint64_t v) {
    uint32_t lo, hi;
    asm("mov.b64 {%0, %1}, %2;" : "=r"(lo), "=r"(hi) : "l"(v));
    return __uint_as_float(lo) + __uint_as_float(hi);
}
__device__ __forceinline__ void unpack2(float& lo, float& hi, uint64_t v) {
    uint32_t l, h;
    asm("mov.b64 {%0, %1}, %2;" : "=r"(l), "=r"(h) : "l"(v));
    lo = __uint_as_float(l); hi = __uint_as_float(h);
}
__device__ __forceinline__ uint64_t h2f2(uint32_t h) {
    __half2 hh = *reinterpret_cast<__half2*>(&h);
    float2 f = __half22float2(hh);
    return pack2(f.x, f.y);
}

// ---------------------------------------------------------------------------
// Split-fp16 conversion: src (R,K) f32 -> dst (R,2K) fp16.
//   A-side (bside=0): [hi | lo];  B-side (bside=1): [hi | hi]
// ---------------------------------------------------------------------------
__global__ __launch_bounds__(256) void split2_kernel(
    const float* __restrict__ src, __half* __restrict__ dst,
    int K, long total, int bside)
{
    long i = ((long)blockIdx.x * blockDim.x + threadIdx.x) * 4;
    if (i >= total) return;
    float4 v = *(const float4*)(src + i);
    int r = (int)(i / K);
    int k = (int)(i - (long)r * K);
    float vv[4] = {v.x, v.y, v.z, v.w};
    __half hi[4], lo[4];
    #pragma unroll
    for (int j = 0; j < 4; j++) {
        hi[j] = __float2half_rn(vv[j]);
        lo[j] = __float2half_rn(vv[j] - __half2float(hi[j]));
    }
    __half2 h01, h23, l01, l23;
    h01.x = hi[0]; h01.y = hi[1]; h23.x = hi[2]; h23.y = hi[3];
    l01.x = lo[0]; l01.y = lo[1]; l23.x = lo[2]; l23.y = lo[3];

    __half* d0 = dst + (size_t)r * (2 * K) + k;
    *(__half2*)(d0)     = h01;
    *(__half2*)(d0 + 2) = h23;
    if (bside == 0) {
        *(__half2*)(d0 + K)     = l01;
        *(__half2*)(d0 + K + 2) = l23;
    } else {
        *(__half2*)(d0 + K)     = h01;
        *(__half2*)(d0 + K + 2) = h23;
    }
}

// ---------------------------------------------------------------------------
// mma.sync fp16 GEMM. half_out selects f16 vs f32 output.
// 128x128 CTA tile, BK=32, 3-stage cp.async, 60KB smem, 2 CTAs/SM.
// ---------------------------------------------------------------------------
#define GSTAGE 20480
#define GEMM_SMEM (3 * GSTAGE)

__global__ __launch_bounds__(256, 2) void gemm_mma(
    const __half* __restrict__ A, const __half* __restrict__ Bw,
    const float* __restrict__ bias, void* __restrict__ Cv,
    int N, int K, int half_out)
{
    extern __shared__ __align__(16) char dsm[];
    const uint32_t smb = smem_u32(dsm);

    const int tid = threadIdx.x;
    const int wid = tid >> 5;
    const int lane = tid & 31;
    const int wm = wid & 3;
    const int wn = wid >> 2;
    const int bm = blockIdx.y * 128;
    const int bn = blockIdx.x * 128;

    const int r0 = tid >> 2;
    const int sg = tid & 3;
    const __half* Ag = A + (size_t)(bm + r0) * K + sg * 8;
    const __half* Bg = Bw + (size_t)(bn + r0) * K + sg * 8;
    const uint32_t ldOff = (uint32_t)(r0 * 80 + sg * 16);
    const size_t rowK64 = (size_t)64 * K;

    const int l15 = lane & 15;
    const uint32_t aOff = (uint32_t)((wm * 32 + l15) * 80 + (lane >> 4) * 16);
    const int bnl = (lane & 7) + ((lane >> 4) & 1) * 8;
    const uint32_t bOff = 10240u + (uint32_t)((wn * 64 + bnl) * 80 + ((lane >> 3) & 1) * 16);

    float acc[2][8][4];
    #pragma unroll
    for (int mf = 0; mf < 2; mf++)
        #pragma unroll
        for (int nf = 0; nf < 8; nf++)
            #pragma unroll
            for (int j = 0; j < 4; j++)
                acc[mf][nf][j] = 0.0f;

    const int nch = K / 32;

    auto load_chunk = [&](int s, int ch) {
        const uint32_t stg = smb + (uint32_t)s * GSTAGE;
        const __half* Ac = Ag + (size_t)ch * 32;
        const __half* Bc = Bg + (size_t)ch * 32;
        cp16(stg + ldOff, Ac);
        cp16(stg + ldOff + 64 * 80, Ac + rowK64);
        cp16(stg + 10240 + ldOff, Bc);
        cp16(stg + 10240 + ldOff + 64 * 80, Bc + rowK64);
    };

    #pragma unroll
    for (int p = 0; p < 2; ++p) {
        load_chunk(p, p);
        asm volatile("cp.async.commit_group;" ::: "memory");
    }

    int sl = 2;
    #pragma unroll 1
    for (int c = 0; c < nch; ++c) {
        asm volatile("cp.async.wait_group 1;" ::: "memory");
        __syncthreads();

        if (c + 2 < nch) load_chunk(sl, c + 2);
        asm volatile("cp.async.commit_group;" ::: "memory");
        sl = (sl == 2) ? 0 : sl + 1;

        const uint32_t so = smb + (uint32_t)((c % 3)) * GSTAGE;
        const uint32_t aA = so + aOff;
        const uint32_t bA = so + bOff;

        #pragma unroll
        for (int ks = 0; ks < 2; ++ks) {
            uint32_t afr[2][4];
            ldsm_x4(afr[0], aA + ks * 32);
            ldsm_x4(afr[1], aA + 16 * 80 + ks * 32);
            uint32_t bfr[4][4];
            #pragma unroll
            for (int nq = 0; nq < 4; ++nq)
                ldsm_x4(bfr[nq], bA + nq * 16 * 80 + ks * 32);

            #pragma unroll
            for (int mf = 0; mf < 2; ++mf)
                #pragma unroll
                for (int nf = 0; nf < 8; ++nf)
                    mma_f16(acc[mf][nf], afr[mf], &bfr[nf >> 1][(nf & 1) * 2]);
        }
    }

    __syncthreads();

    const int erow = lane >> 2;
    const int ecol = (lane & 3) * 2;
    #pragma unroll
    for (int mf = 0; mf < 2; ++mf) {
        const int row = bm + wm * 32 + mf * 16 + erow;
        #pragma unroll
        for (int nf = 0; nf < 8; ++nf) {
            const int col = bn + wn * 64 + nf * 8 + ecol;
            float2 bb = *(const float2*)(bias + col);
            float o0x = acc[mf][nf][0] + bb.x;
            float o0y = acc[mf][nf][1] + bb.y;
            float o1x = acc[mf][nf][2] + bb.x;
            float o1y = acc[mf][nf][3] + bb.y;
            if (half_out) {
                __half* C = (__half*)Cv;
                *(__half2*)(C + (size_t)row * N + col) = __floats2half2_rn(o0x, o0y);
                *(__half2*)(C + (size_t)(row + 8) * N + col) = __floats2half2_rn(o1x, o1y);
            } else {
                float* C = (float*)Cv;
                *(float2*)(C + (size_t)row * N + col) = make_float2(o0x, o0y);
                *(float2*)(C + (size_t)(row + 8) * N + col) = make_float2(o1x, o1y);
            }
        }
    }
}

// ---------------------------------------------------------------------------
// Phase A: local state over sub-segment m (256 steps, k/v only, fp16 qkv).
// Block = 512 threads = 16 warps = all 64 rows of one (b,h).
// smem: k 2x8KB + v 2x8KB = 32KB (fp16).
// ---------------------------------------------------------------------------
#define PHA_SMEM 32768

__global__ __launch_bounds__(512) void stp_phaseA(
    const float* __restrict__ Lam,
    const float* __restrict__ Gam)
{
    extern __shared__ __align__(16) __half smh[];
    const uint32_t smb = smem_u32(smh);

    const int bh = blockIdx.x;
    const int m = blockIdx.y;            // sub-segment 0..13
    const int b = bh >> 4;
    const int h = bh & 15;
    const int tid = threadIdx.x;
    const int wid = tid >> 5;
    const int lane = tid & 31;
    const int rg = lane >> 3;
    const int cg = lane & 7;
    const int i = (wid << 2) + rg;       // row 0..63
    const int j0 = cg << 3;

    uint64_t S2[4], r2[4], g2[4];
    {
        const int pbase = (h * Nd + i) * Nd + j0;
        float lv[8], gv[8];
        *(float4*)(lv)     = *(const float4*)(Lam + pbase);
        *(float4*)(lv + 4) = *(const float4*)(Lam + pbase + 4);
        *(float4*)(gv)     = *(const float4*)(Gam + pbase);
        *(float4*)(gv + 4) = *(const float4*)(Gam + pbase + 4);
        float rr[8], gg[8];
        #pragma unroll
        for (int jj = 0; jj < 8; jj++) {
            float sgm = 1.0f / (1.0f + __expf(-lv[jj]));
            rr[jj] = 1.0f - sgm;
            gg[jj] = gv[jj] * 0.125f;
        }
        #pragma unroll
        for (int q = 0; q < 4; q++) {
            r2[q] = pack2(rr[2 * q], rr[2 * q + 1]);
            g2[q] = pack2(gg[2 * q], gg[2 * q + 1]);
            S2[q] = 0ull;
        }
    }

    const __half* gq = g_qkv + (size_t)b * NL * 3 * ND + h * Nd;
    const int tseg = m * SUBA;

    // stage layout (half indices): k: s*4096 ; v: 8192 + s*4096
    const int lst = tid >> 3;            // 0..63 step
    const int lsg = (tid & 7) * 8;       // half offset within 64
    auto load_chunk = [&](int s, int t0) {
        const __half* src = gq + (size_t)(t0 + lst) * (3 * ND) + lsg;
        const uint32_t o = (uint32_t)(lst * 64 + lsg) * 2;
        cp16(smb + (uint32_t)s * 8192u + o, src + ND);            // k
        cp16(smb + 16384u + (uint32_t)s * 8192u + o, src + 2 * ND); // v
        asm volatile("cp.async.commit_group;" ::: "memory");
    };

    load_chunk(0, tseg);

    const int NCA = SUBA / 64;   // 4 chunks of 64 steps
    #pragma unroll 1
    for (int c = 0; c < NCA; ++c) {
        if (c + 1 < NCA) {
            load_chunk((c + 1) & 1, tseg + (c + 1) * 64);
            asm volatile("cp.async.wait_group 1;" ::: "memory");
        } else {
            asm volatile("cp.async.wait_group 0;" ::: "memory");
        }
        __syncthreads();

        const int s = c & 1;
        const __half* ks = smh + s * 4096;
        const __half* vs = smh + 8192 + s * 4096;

        #pragma unroll 4
        for (int tt = 0; tt < 64; ++tt) {
            uint4 kraw = *(const uint4*)(ks + (tt << 6) + j0);
            const float cv = __half2float(vs[(tt << 6) + i]);
            const uint64_t v2 = pack2(cv, cv);
            uint64_t k2[4] = {h2f2(kraw.x), h2f2(kraw.y), h2f2(kraw.z), h2f2(kraw.w)};
            #pragma unroll
            for (int q = 0; q < 4; ++q) {
                uint64_t vk = mul2(v2, k2[q]);
                S2[q] = fma2(r2[q], S2[q], mul2(g2[q], vk));
            }
        }
        __syncthreads();
    }

    float* F = g_fst + ((size_t)m * 64 + bh) * 4096 + i * 64 + j0;
    float f[8];
    #pragma unroll
    for (int q = 0; q < 4; ++q) unpack2(f[2 * q], f[2 * q + 1], S2[q]);
    *(float4*)(F)     = *(float4*)(f);
    *(float4*)(F + 4) = *(float4*)(f + 4);
}

// ---------------------------------------------------------------------------
// Combine: Horner over 14 sub-segment states -> segment-init states U_s.
// ---------------------------------------------------------------------------
__global__ __launch_bounds__(256) void stp_combine(const float* __restrict__ Lam)
{
    const int e = blockIdx.x * 256 + threadIdx.x;   // 0..262143
    const int bh = e >> 12;
    const int idx = e & 4095;
    const int h = bh & 15;

    const float lam = Lam[h * 4096 + idx];
    const float sgm = 1.0f / (1.0f + __expf(-lam));
    float r = 1.0f - sgm;
    float r256 = r;
    #pragma unroll
    for (int q = 0; q < 8; q++) r256 *= r256;   // r^256

    float U = 0.0f;
    #pragma unroll
    for (int m = 0; m < NSUBA; ++m) {
        if (m > 0 && (m & 1) == 0)
            g_ust[((size_t)(m >> 1) * 64 + bh) * 4096 + idx] = U;
        U = r256 * U + g_fst[((size_t)m * 64 + bh) * 4096 + idx];
    }
    g_ust[((size_t)7 * 64 + bh) * 4096 + idx] = U;
}

// ---------------------------------------------------------------------------
// Phase B: full scan of segment p (512 steps) with true initial state.
// Block = 512 threads = all 64 rows of one (b,h). fp16 qkv staging.
// smem: q,k,v 2x8KB each = 48KB. Writes y split-fp16 into g_sA.
// ---------------------------------------------------------------------------
#define PHB_SMEM 49152

__global__ __launch_bounds__(512) void stp_phaseB(
    const float* __restrict__ Wst,
    const float* __restrict__ Lam,
    const float* __restrict__ Gam)
{
    extern __shared__ __align__(16) __half smh[];
    const uint32_t smb = smem_u32(smh);

    const int bh = blockIdx.x;
    const int p = blockIdx.y;            // segment 0..7
    const int b = bh >> 4;
    const int h = bh & 15;
    const int tid = threadIdx.x;
    const int wid = tid >> 5;
    const int lane = tid & 31;
    const int rg = lane >> 3;
    const int cg = lane & 7;
    const int i = (wid << 2) + rg;       // row 0..63
    const int j0 = cg << 3;

    uint64_t u2[4], r2[4], g2[4], cw2[4];
    {
        const int pbase = (h * Nd + i) * Nd + j0;
        float wv[8], lv[8], gv[8];
        *(float4*)(wv)     = *(const float4*)(Wst + pbase);
        *(float4*)(wv + 4) = *(const float4*)(Wst + pbase + 4);
        *(float4*)(lv)     = *(const float4*)(Lam + pbase);
        *(float4*)(lv + 4) = *(const float4*)(Lam + pbase + 4);
        *(float4*)(gv)     = *(const float4*)(Gam + pbase);
        *(float4*)(gv + 4) = *(const float4*)(Gam + pbase + 4);
        float rr[8], gg[8], cc[8];
        #pragma unroll
        for (int jj = 0; jj < 8; jj++) {
            float sgm = 1.0f / (1.0f + __expf(-lv[jj]));
            rr[jj] = 1.0f - sgm;
            cc[jj] = sgm * wv[jj];
            gg[jj] = gv[jj] * 0.125f;
        }

        float U[8] = {0, 0, 0, 0, 0, 0, 0, 0};
        if (p > 0) {
            const float* Up = g_ust + ((size_t)p * 64 + bh) * 4096 + i * 64 + j0;
            *(float4*)(U)     = *(const float4*)(Up);
            *(float4*)(U + 4) = *(const float4*)(Up + 4);
        }

        #pragma unroll
        for (int q = 0; q < 4; q++) {
            u2[q]  = pack2(wv[2 * q] + U[2 * q], wv[2 * q + 1] + U[2 * q + 1]);
            r2[q]  = pack2(rr[2 * q], rr[2 * q + 1]);
            g2[q]  = pack2(gg[2 * q], gg[2 * q + 1]);
            cw2[q] = pack2(cc[2 * q], cc[2 * q + 1]);
        }
    }

    const __half* gq = g_qkv + (size_t)b * NL * 3 * ND + h * Nd;
    __half* ybase = g_sA + (size_t)(b * NL) * K2 + (h * 64 + i);
    const int tseg = p * SEGB;

    // stage layout (half indices): q: s*4096 ; k: 8192 + s*4096 ; v: 16384 + s*4096
    const int lst = tid >> 3;
    const int lsg = (tid & 7) * 8;
    auto load_chunk = [&](int s, int t0) {
        const __half* src = gq + (size_t)(t0 + lst) * (3 * ND) + lsg;
        const uint32_t o = (uint32_t)(lst * 64 + lsg) * 2 + (uint32_t)s * 8192u;
        cp16(smb + o, src);                       // q
        cp16(smb + 16384u + o, src + ND);         // k
        cp16(smb + 32768u + o, src + 2 * ND);     // v
        asm volatile("cp.async.commit_group;" ::: "memory");
    };

    load_chunk(0, tseg);

    const int NCB = SEGB / 64;   // 8 chunks of 64 steps
    #pragma unroll 1
    for (int c = 0; c < NCB; ++c) {
        if (c + 1 < NCB) {
            load_chunk((c + 1) & 1, tseg + (c + 1) * 64);
            asm volatile("cp.async.wait_group 1;" ::: "memory");
        } else {
            asm volatile("cp.async.wait_group 0;" ::: "memory");
        }
        __syncthreads();

        const int s = c & 1;
        const __half* qs = smh + s * 4096;
        const __half* ks = smh + 8192 + s * 4096;
        const __half* vs = smh + 16384 + s * 4096;

        #pragma unroll 1
        for (int tt0 = 0; tt0 < 64; tt0 += 8) {
            float yps[8];
            #pragma unroll
            for (int ss = 0; ss < 8; ++ss) {
                const int tt = tt0 + ss;
                uint4 qraw = *(const uint4*)(qs + (tt << 6) + j0);
                uint4 kraw = *(const uint4*)(ks + (tt << 6) + j0);
                const float cv = __half2float(vs[(tt << 6) + i]);
                const uint64_t v2 = pack2(cv, cv);
                uint64_t q2[4] = {h2f2(qraw.x), h2f2(qraw.y), h2f2(qraw.z), h2f2(qraw.w)};
                uint64_t k2[4] = {h2f2(kraw.x), h2f2(kraw.y), h2f2(kraw.z), h2f2(kraw.w)};

                uint64_t acc = 0ull;
                #pragma unroll
                for (int q = 0; q < 4; ++q) {
                    uint64_t vk = mul2(v2, k2[q]);
                    uint64_t tmp = fma2(g2[q], vk, cw2[q]);
                    u2[q] = fma2(r2[q], u2[q], tmp);
                    acc = fma2(u2[q], q2[q], acc);
                }
                yps[ss] = hadd2(acc);
            }

            #pragma unroll
            for (int ss = 0; ss < 8; ++ss) yps[ss] += __shfl_xor_sync(0xffffffffu, yps[ss], 1);
            #pragma unroll
            for (int ss = 0; ss < 8; ++ss) yps[ss] += __shfl_xor_sync(0xffffffffu, yps[ss], 2);
            #pragma unroll
            for (int ss = 0; ss < 8; ++ss) yps[ss] += __shfl_xor_sync(0xffffffffu, yps[ss], 4);

            if (cg == 0) {
                const size_t t0g = (size_t)tseg + c * 64 + tt0;
                #pragma unroll
                for (int ss = 0; ss < 8; ++ss) {
                    __half hi = __float2half_rn(yps[ss]);
                    __half lo = __float2half_rn(yps[ss] - __half2float(hi));
                    __half* yp = ybase + (t0g + ss) * K2;
                    yp[0] = hi;
                    yp[ND] = lo;
                }
            }
        }
        __syncthreads();
    }
}

// ---------------------------------------------------------------------------

extern "C" void kernel_launch(void* const* d_in, const int* in_sizes, int n_in,
                              void* d_out, int out_size)
{
    const float* x          = (const float*)d_in[0];
    const float* Wqkv_w     = (const float*)d_in[1];
    const float* Wqkv_b     = (const float*)d_in[2];
    const float* out_w      = (const float*)d_in[3];
    const float* out_b      = (const float*)d_in[4];
    const float* W_static   = (const float*)d_in[5];
    const float* Lambda_raw = (const float*)d_in[6];
    const float* Gamma      = (const float*)d_in[7];

    __half* qkv = nullptr;
    __half *sA = nullptr, *sB1 = nullptr, *sB2 = nullptr;
    cudaGetSymbolAddress((void**)&qkv, g_qkv);
    cudaGetSymbolAddress((void**)&sA, g_sA);
    cudaGetSymbolAddress((void**)&sB1, g_sB1);
    cudaGetSymbolAddress((void**)&sB2, g_sB2);

    static bool attr_set = false;
    if (!attr_set) {
        cudaFuncSetAttribute(gemm_mma, cudaFuncAttributeMaxDynamicSharedMemorySize, GEMM_SMEM);
        cudaFuncSetAttribute(stp_phaseA, cudaFuncAttributeMaxDynamicSharedMemorySize, PHA_SMEM);
        cudaFuncSetAttribute(stp_phaseB, cudaFuncAttributeMaxDynamicSharedMemorySize, PHB_SMEM);
        attr_set = true;
    }

    const long nx = (long)MTOT * ND;
    const long nw1 = (long)3 * ND * ND;
    const long nw2 = (long)ND * ND;

    // split x -> sA (A-side), Wqkv_w -> sB1 (B-side)
    split2_kernel<<<(unsigned)((nx / 4 + 255) / 256), 256>>>(x, sA, ND, nx, 0);
    split2_kernel<<<(unsigned)((nw1 / 4 + 255) / 256), 256>>>(Wqkv_w, sB1, ND, nw1, 1);
    // qkv (fp16) = x @ Wqkv_w^T + b
    gemm_mma<<<dim3(3 * ND / 128, MTOT / 128), 256, GEMM_SMEM>>>(
        sA, sB1, Wqkv_b, qkv, 3 * ND, K2, 1);

    // segmented scan: phase A -> combine -> phase B (writes split y into sA)
    stp_phaseA<<<dim3(NB * NH, NSUBA), 512, PHA_SMEM>>>(Lambda_raw, Gamma);
    stp_combine<<<1024, 256>>>(Lambda_raw);
    stp_phaseB<<<dim3(NB * NH, 8), 512, PHB_SMEM>>>(W_static, Lambda_raw, Gamma);

    // split out_w -> sB2 (B-side); out = y @ out_w^T + b (f32)
    split2_kernel<<<(unsigned)((nw2 / 4 + 255) / 256), 256>>>(out_w, sB2, ND, nw2, 1);
    gemm_mma<<<dim3(ND / 128, MTOT / 128), 256, GEMM_SMEM>>>(
        sA, sB2, out_b, d_out, ND, K2, 0);
}

// round 9
// speedup vs baseline: 5.8446x; 1.4337x over previous
#include <cuda_runtime.h>
#include <cuda_fp16.h>
#include <cstdint>

#define NB 4
#define NL 4096
#define NH 16
#define ND 1024
#define Nd 64
#define MTOT (NB * NL)          // 16384
#define SEGB 512                // phase-B segment length
#define SUBA 256                // phase-A sub-segment length
#define NSUBA 14                // sub-segments covering [0, 3584)

// ---------------------------------------------------------------------------
// Device-global scratch (no allocations allowed)
// ---------------------------------------------------------------------------
__device__ __half g_qkv[(size_t)NB * NL * 3 * ND];   // fp16 qkv
__device__ float g_fst[(size_t)NSUBA * 64 * 4096];   // sub-segment local states
__device__ float g_ust[(size_t)8 * 64 * 4096];       // segment-init states
__device__ __half g_sA[(size_t)MTOT * ND];           // fp16 A (x, then y)
__device__ __half g_sB1[(size_t)3 * ND * ND];        // fp16 Wqkv_w
__device__ __half g_sB2[(size_t)ND * ND];            // fp16 out_w

// ---------------------------------------------------------------------------
__device__ __forceinline__ uint32_t smem_u32(const void* p) {
    uint32_t a;
    asm("{ .reg .u64 t; cvta.to.shared.u64 t, %1; cvt.u32.u64 %0, t; }"
        : "=r"(a) : "l"(p));
    return a;
}
__device__ __forceinline__ void ldsm_x4(uint32_t* r, uint32_t addr) {
    asm volatile("ldmatrix.sync.aligned.m8n8.x4.shared.b16 {%0,%1,%2,%3}, [%4];"
                 : "=r"(r[0]), "=r"(r[1]), "=r"(r[2]), "=r"(r[3]) : "r"(addr));
}
__device__ __forceinline__ void mma_f16(float* d, const uint32_t* a, const uint32_t* b) {
    asm volatile(
        "mma.sync.aligned.m16n8k16.row.col.f32.f16.f16.f32 "
        "{%0,%1,%2,%3}, {%4,%5,%6,%7}, {%8,%9}, {%0,%1,%2,%3};"
        : "+f"(d[0]), "+f"(d[1]), "+f"(d[2]), "+f"(d[3])
        : "r"(a[0]), "r"(a[1]), "r"(a[2]), "r"(a[3]), "r"(b[0]), "r"(b[1]));
}
__device__ __forceinline__ void cp16(uint32_t saddr, const void* gaddr) {
    asm volatile("cp.async.cg.shared.global [%0], [%1], 16;" :: "r"(saddr), "l"(gaddr));
}
__device__ __forceinline__ uint64_t mul2(uint64_t a, uint64_t b) {
    uint64_t d; asm("mul.rn.f32x2 %0, %1, %2;" : "=l"(d) : "l"(a), "l"(b)); return d;
}
__device__ __forceinline__ uint64_t fma2(uint64_t a, uint64_t b, uint64_t c) {
    uint64_t d; asm("fma.rn.f32x2 %0, %1, %2, %3;" : "=l"(d) : "l"(a), "l"(b), "l"(c)); return d;
}
__device__ __forceinline__ uint64_t pack2(float lo, float hi) {
    uint64_t d;
    asm("mov.b64 %0, {%1, %2};" : "=l"(d) : "r"(__float_as_uint(lo)), "r"(__float_as_uint(hi)));
    return d;
}
__device__ __forceinline__ float hadd2(uint64_t v) {
    uint32_t lo, hi;
    asm("mov.b64 {%0, %1}, %2;" : "=r"(lo), "=r"(hi) : "l"(v));
    return __uint_as_float(lo) + __uint_as_float(hi);
}
__device__ __forceinline__ void unpack2(float& lo, float& hi, uint64_t v) {
    uint32_t l, h;
    asm("mov.b64 {%0, %1}, %2;" : "=r"(l), "=r"(h) : "l"(v));
    lo = __uint_as_float(l); hi = __uint_as_float(h);
}
__device__ __forceinline__ uint64_t h2f2(uint32_t h) {
    __half2 hh = *reinterpret_cast<__half2*>(&h);
    float2 f = __half22float2(hh);
    return pack2(f.x, f.y);
}

// ---------------------------------------------------------------------------
// Plain f32 -> f16 convert (8 elems/thread).
// ---------------------------------------------------------------------------
__global__ __launch_bounds__(256) void cvt16_kernel(
    const float* __restrict__ src, __half* __restrict__ dst, long total)
{
    long i = ((long)blockIdx.x * blockDim.x + threadIdx.x) * 8;
    if (i >= total) return;
    float4 a = *(const float4*)(src + i);
    float4 b = *(const float4*)(src + i + 4);
    __half2 o[4];
    o[0] = __floats2half2_rn(a.x, a.y);
    o[1] = __floats2half2_rn(a.z, a.w);
    o[2] = __floats2half2_rn(b.x, b.y);
    o[3] = __floats2half2_rn(b.z, b.w);
    *(uint4*)(dst + i) = *(uint4*)o;
}

// ---------------------------------------------------------------------------
// mma.sync fp16 GEMM. half_out selects f16 vs f32 output.
// 128x128 CTA tile, BK=32, 3-stage cp.async, 60KB smem, 2 CTAs/SM.
// ---------------------------------------------------------------------------
#define GSTAGE 20480
#define GEMM_SMEM (3 * GSTAGE)

__global__ __launch_bounds__(256, 2) void gemm_mma(
    const __half* __restrict__ A, const __half* __restrict__ Bw,
    const float* __restrict__ bias, void* __restrict__ Cv,
    int N, int K, int half_out)
{
    extern __shared__ __align__(16) char dsm[];
    const uint32_t smb = smem_u32(dsm);

    const int tid = threadIdx.x;
    const int wid = tid >> 5;
    const int lane = tid & 31;
    const int wm = wid & 3;
    const int wn = wid >> 2;
    const int bm = blockIdx.y * 128;
    const int bn = blockIdx.x * 128;

    const int r0 = tid >> 2;
    const int sg = tid & 3;
    const __half* Ag = A + (size_t)(bm + r0) * K + sg * 8;
    const __half* Bg = Bw + (size_t)(bn + r0) * K + sg * 8;
    const uint32_t ldOff = (uint32_t)(r0 * 80 + sg * 16);
    const size_t rowK64 = (size_t)64 * K;

    const int l15 = lane & 15;
    const uint32_t aOff = (uint32_t)((wm * 32 + l15) * 80 + (lane >> 4) * 16);
    const int bnl = (lane & 7) + ((lane >> 4) & 1) * 8;
    const uint32_t bOff = 10240u + (uint32_t)((wn * 64 + bnl) * 80 + ((lane >> 3) & 1) * 16);

    float acc[2][8][4];
    #pragma unroll
    for (int mf = 0; mf < 2; mf++)
        #pragma unroll
        for (int nf = 0; nf < 8; nf++)
            #pragma unroll
            for (int j = 0; j < 4; j++)
                acc[mf][nf][j] = 0.0f;

    const int nch = K / 32;

    auto load_chunk = [&](int s, int ch) {
        const uint32_t stg = smb + (uint32_t)s * GSTAGE;
        const __half* Ac = Ag + (size_t)ch * 32;
        const __half* Bc = Bg + (size_t)ch * 32;
        cp16(stg + ldOff, Ac);
        cp16(stg + ldOff + 64 * 80, Ac + rowK64);
        cp16(stg + 10240 + ldOff, Bc);
        cp16(stg + 10240 + ldOff + 64 * 80, Bc + rowK64);
    };

    #pragma unroll
    for (int p = 0; p < 2; ++p) {
        load_chunk(p, p);
        asm volatile("cp.async.commit_group;" ::: "memory");
    }

    int sl = 2;
    #pragma unroll 1
    for (int c = 0; c < nch; ++c) {
        asm volatile("cp.async.wait_group 1;" ::: "memory");
        __syncthreads();

        if (c + 2 < nch) load_chunk(sl, c + 2);
        asm volatile("cp.async.commit_group;" ::: "memory");
        sl = (sl == 2) ? 0 : sl + 1;

        const uint32_t so = smb + (uint32_t)((c % 3)) * GSTAGE;
        const uint32_t aA = so + aOff;
        const uint32_t bA = so + bOff;

        #pragma unroll
        for (int ks = 0; ks < 2; ++ks) {
            uint32_t afr[2][4];
            ldsm_x4(afr[0], aA + ks * 32);
            ldsm_x4(afr[1], aA + 16 * 80 + ks * 32);
            uint32_t bfr[4][4];
            #pragma unroll
            for (int nq = 0; nq < 4; ++nq)
                ldsm_x4(bfr[nq], bA + nq * 16 * 80 + ks * 32);

            #pragma unroll
            for (int mf = 0; mf < 2; ++mf)
                #pragma unroll
                for (int nf = 0; nf < 8; ++nf)
                    mma_f16(acc[mf][nf], afr[mf], &bfr[nf >> 1][(nf & 1) * 2]);
        }
    }

    __syncthreads();

    const int erow = lane >> 2;
    const int ecol = (lane & 3) * 2;
    #pragma unroll
    for (int mf = 0; mf < 2; ++mf) {
        const int row = bm + wm * 32 + mf * 16 + erow;
        #pragma unroll
        for (int nf = 0; nf < 8; ++nf) {
            const int col = bn + wn * 64 + nf * 8 + ecol;
            float2 bb = *(const float2*)(bias + col);
            float o0x = acc[mf][nf][0] + bb.x;
            float o0y = acc[mf][nf][1] + bb.y;
            float o1x = acc[mf][nf][2] + bb.x;
            float o1y = acc[mf][nf][3] + bb.y;
            if (half_out) {
                __half* C = (__half*)Cv;
                *(__half2*)(C + (size_t)row * N + col) = __floats2half2_rn(o0x, o0y);
                *(__half2*)(C + (size_t)(row + 8) * N + col) = __floats2half2_rn(o1x, o1y);
            } else {
                float* C = (float*)Cv;
                *(float2*)(C + (size_t)row * N + col) = make_float2(o0x, o0y);
                *(float2*)(C + (size_t)(row + 8) * N + col) = make_float2(o1x, o1y);
            }
        }
    }
}

// ---------------------------------------------------------------------------
// Phase A: local state over sub-segment m (256 steps, k/v only, fp16 qkv).
// Block = 512 threads = 16 warps = all 64 rows of one (b,h).
// ---------------------------------------------------------------------------
#define PHA_SMEM 32768

__global__ __launch_bounds__(512) void stp_phaseA(
    const float* __restrict__ Lam,
    const float* __restrict__ Gam)
{
    extern __shared__ __align__(16) __half smh[];
    const uint32_t smb = smem_u32(smh);

    const int bh = blockIdx.x;
    const int m = blockIdx.y;            // sub-segment 0..13
    const int b = bh >> 4;
    const int h = bh & 15;
    const int tid = threadIdx.x;
    const int wid = tid >> 5;
    const int lane = tid & 31;
    const int rg = lane >> 3;
    const int cg = lane & 7;
    const int i = (wid << 2) + rg;       // row 0..63
    const int j0 = cg << 3;

    uint64_t S2[4], r2[4], g2[4];
    {
        const int pbase = (h * Nd + i) * Nd + j0;
        float lv[8], gv[8];
        *(float4*)(lv)     = *(const float4*)(Lam + pbase);
        *(float4*)(lv + 4) = *(const float4*)(Lam + pbase + 4);
        *(float4*)(gv)     = *(const float4*)(Gam + pbase);
        *(float4*)(gv + 4) = *(const float4*)(Gam + pbase + 4);
        float rr[8], gg[8];
        #pragma unroll
        for (int jj = 0; jj < 8; jj++) {
            float sgm = 1.0f / (1.0f + __expf(-lv[jj]));
            rr[jj] = 1.0f - sgm;
            gg[jj] = gv[jj] * 0.125f;
        }
        #pragma unroll
        for (int q = 0; q < 4; q++) {
            r2[q] = pack2(rr[2 * q], rr[2 * q + 1]);
            g2[q] = pack2(gg[2 * q], gg[2 * q + 1]);
            S2[q] = 0ull;
        }
    }

    const __half* gq = g_qkv + (size_t)b * NL * 3 * ND + h * Nd;
    const int tseg = m * SUBA;

    const int lst = tid >> 3;            // 0..63 step
    const int lsg = (tid & 7) * 8;       // half offset within 64
    auto load_chunk = [&](int s, int t0) {
        const __half* src = gq + (size_t)(t0 + lst) * (3 * ND) + lsg;
        const uint32_t o = (uint32_t)(lst * 64 + lsg) * 2;
        cp16(smb + (uint32_t)s * 8192u + o, src + ND);              // k
        cp16(smb + 16384u + (uint32_t)s * 8192u + o, src + 2 * ND); // v
        asm volatile("cp.async.commit_group;" ::: "memory");
    };

    load_chunk(0, tseg);

    const int NCA = SUBA / 64;   // 4 chunks of 64 steps
    #pragma unroll 1
    for (int c = 0; c < NCA; ++c) {
        if (c + 1 < NCA) {
            load_chunk((c + 1) & 1, tseg + (c + 1) * 64);
            asm volatile("cp.async.wait_group 1;" ::: "memory");
        } else {
            asm volatile("cp.async.wait_group 0;" ::: "memory");
        }
        __syncthreads();

        const int s = c & 1;
        const __half* ks = smh + s * 4096;
        const __half* vs = smh + 8192 + s * 4096;

        #pragma unroll 4
        for (int tt = 0; tt < 64; ++tt) {
            uint4 kraw = *(const uint4*)(ks + (tt << 6) + j0);
            const float cv = __half2float(vs[(tt << 6) + i]);
            const uint64_t v2 = pack2(cv, cv);
            uint64_t k2[4] = {h2f2(kraw.x), h2f2(kraw.y), h2f2(kraw.z), h2f2(kraw.w)};
            #pragma unroll
            for (int q = 0; q < 4; ++q) {
                uint64_t vk = mul2(v2, k2[q]);
                S2[q] = fma2(r2[q], S2[q], mul2(g2[q], vk));
            }
        }
        __syncthreads();
    }

    float* F = g_fst + ((size_t)m * 64 + bh) * 4096 + i * 64 + j0;
    float f[8];
    #pragma unroll
    for (int q = 0; q < 4; ++q) unpack2(f[2 * q], f[2 * q + 1], S2[q]);
    *(float4*)(F)     = *(float4*)(f);
    *(float4*)(F + 4) = *(float4*)(f + 4);
}

// ---------------------------------------------------------------------------
// Combine: Horner over 14 sub-segment states -> segment-init states U_s.
// ---------------------------------------------------------------------------
__global__ __launch_bounds__(256) void stp_combine(const float* __restrict__ Lam)
{
    const int e = blockIdx.x * 256 + threadIdx.x;   // 0..262143
    const int bh = e >> 12;
    const int idx = e & 4095;
    const int h = bh & 15;

    const float lam = Lam[h * 4096 + idx];
    const float sgm = 1.0f / (1.0f + __expf(-lam));
    float r = 1.0f - sgm;
    float r256 = r;
    #pragma unroll
    for (int q = 0; q < 8; q++) r256 *= r256;   // r^256

    float U = 0.0f;
    #pragma unroll
    for (int m = 0; m < NSUBA; ++m) {
        if (m > 0 && (m & 1) == 0)
            g_ust[((size_t)(m >> 1) * 64 + bh) * 4096 + idx] = U;
        U = r256 * U + g_fst[((size_t)m * 64 + bh) * 4096 + idx];
    }
    g_ust[((size_t)7 * 64 + bh) * 4096 + idx] = U;
}

// ---------------------------------------------------------------------------
// Phase B: full scan of segment p (512 steps) with true initial state.
// Block = 512 threads = all 64 rows of one (b,h). Writes y fp16 into g_sA.
// ---------------------------------------------------------------------------
#define PHB_SMEM 49152

__global__ __launch_bounds__(512) void stp_phaseB(
    const float* __restrict__ Wst,
    const float* __restrict__ Lam,
    const float* __restrict__ Gam)
{
    extern __shared__ __align__(16) __half smh[];
    const uint32_t smb = smem_u32(smh);

    const int bh = blockIdx.x;
    const int p = blockIdx.y;            // segment 0..7
    const int b = bh >> 4;
    const int h = bh & 15;
    const int tid = threadIdx.x;
    const int wid = tid >> 5;
    const int lane = tid & 31;
    const int rg = lane >> 3;
    const int cg = lane & 7;
    const int i = (wid << 2) + rg;       // row 0..63
    const int j0 = cg << 3;

    uint64_t u2[4], r2[4], g2[4], cw2[4];
    {
        const int pbase = (h * Nd + i) * Nd + j0;
        float wv[8], lv[8], gv[8];
        *(float4*)(wv)     = *(const float4*)(Wst + pbase);
        *(float4*)(wv + 4) = *(const float4*)(Wst + pbase + 4);
        *(float4*)(lv)     = *(const float4*)(Lam + pbase);
        *(float4*)(lv + 4) = *(const float4*)(Lam + pbase + 4);
        *(float4*)(gv)     = *(const float4*)(Gam + pbase);
        *(float4*)(gv + 4) = *(const float4*)(Gam + pbase + 4);
        float rr[8], gg[8], cc[8];
        #pragma unroll
        for (int jj = 0; jj < 8; jj++) {
            float sgm = 1.0f / (1.0f + __expf(-lv[jj]));
            rr[jj] = 1.0f - sgm;
            cc[jj] = sgm * wv[jj];
            gg[jj] = gv[jj] * 0.125f;
        }

        float U[8] = {0, 0, 0, 0, 0, 0, 0, 0};
        if (p > 0) {
            const float* Up = g_ust + ((size_t)p * 64 + bh) * 4096 + i * 64 + j0;
            *(float4*)(U)     = *(const float4*)(Up);
            *(float4*)(U + 4) = *(const float4*)(Up + 4);
        }

        #pragma unroll
        for (int q = 0; q < 4; q++) {
            u2[q]  = pack2(wv[2 * q] + U[2 * q], wv[2 * q + 1] + U[2 * q + 1]);
            r2[q]  = pack2(rr[2 * q], rr[2 * q + 1]);
            g2[q]  = pack2(gg[2 * q], gg[2 * q + 1]);
            cw2[q] = pack2(cc[2 * q], cc[2 * q + 1]);
        }
    }

    const __half* gq = g_qkv + (size_t)b * NL * 3 * ND + h * Nd;
    __half* ybase = g_sA + (size_t)(b * NL) * ND + (h * 64 + i);
    const int tseg = p * SEGB;

    const int lst = tid >> 3;
    const int lsg = (tid & 7) * 8;
    auto load_chunk = [&](int s, int t0) {
        const __half* src = gq + (size_t)(t0 + lst) * (3 * ND) + lsg;
        const uint32_t o = (uint32_t)(lst * 64 + lsg) * 2 + (uint32_t)s * 8192u;
        cp16(smb + o, src);                       // q
        cp16(smb + 16384u + o, src + ND);         // k
        cp16(smb + 32768u + o, src + 2 * ND);     // v
        asm volatile("cp.async.commit_group;" ::: "memory");
    };

    load_chunk(0, tseg);

    const int NCB = SEGB / 64;   // 8 chunks of 64 steps
    #pragma unroll 1
    for (int c = 0; c < NCB; ++c) {
        if (c + 1 < NCB) {
            load_chunk((c + 1) & 1, tseg + (c + 1) * 64);
            asm volatile("cp.async.wait_group 1;" ::: "memory");
        } else {
            asm volatile("cp.async.wait_group 0;" ::: "memory");
        }
        __syncthreads();

        const int s = c & 1;
        const __half* qs = smh + s * 4096;
        const __half* ks = smh + 8192 + s * 4096;
        const __half* vs = smh + 16384 + s * 4096;

        #pragma unroll 1
        for (int tt0 = 0; tt0 < 64; tt0 += 8) {
            float yps[8];
            #pragma unroll
            for (int ss = 0; ss < 8; ++ss) {
                const int tt = tt0 + ss;
                uint4 qraw = *(const uint4*)(qs + (tt << 6) + j0);
                uint4 kraw = *(const uint4*)(ks + (tt << 6) + j0);
                const float cv = __half2float(vs[(tt << 6) + i]);
                const uint64_t v2 = pack2(cv, cv);
                uint64_t q2[4] = {h2f2(qraw.x), h2f2(qraw.y), h2f2(qraw.z), h2f2(qraw.w)};
                uint64_t k2[4] = {h2f2(kraw.x), h2f2(kraw.y), h2f2(kraw.z), h2f2(kraw.w)};

                uint64_t acc = 0ull;
                #pragma unroll
                for (int q = 0; q < 4; ++q) {
                    uint64_t vk = mul2(v2, k2[q]);
                    uint64_t tmp = fma2(g2[q], vk, cw2[q]);
                    u2[q] = fma2(r2[q], u2[q], tmp);
                    acc = fma2(u2[q], q2[q], acc);
                }
                yps[ss] = hadd2(acc);
            }

            #pragma unroll
            for (int ss = 0; ss < 8; ++ss) yps[ss] += __shfl_xor_sync(0xffffffffu, yps[ss], 1);
            #pragma unroll
            for (int ss = 0; ss < 8; ++ss) yps[ss] += __shfl_xor_sync(0xffffffffu, yps[ss], 2);
            #pragma unroll
            for (int ss = 0; ss < 8; ++ss) yps[ss] += __shfl_xor_sync(0xffffffffu, yps[ss], 4);

            if (cg == 0) {
                const size_t t0g = (size_t)tseg + c * 64 + tt0;
                #pragma unroll
                for (int ss = 0; ss < 8; ++ss)
                    ybase[(t0g + ss) * ND] = __float2half_rn(yps[ss]);
            }
        }
        __syncthreads();
    }
}

// ---------------------------------------------------------------------------

extern "C" void kernel_launch(void* const* d_in, const int* in_sizes, int n_in,
                              void* d_out, int out_size)
{
    const float* x          = (const float*)d_in[0];
    const float* Wqkv_w     = (const float*)d_in[1];
    const float* Wqkv_b     = (const float*)d_in[2];
    const float* out_w      = (const float*)d_in[3];
    const float* out_b      = (const float*)d_in[4];
    const float* W_static   = (const float*)d_in[5];
    const float* Lambda_raw = (const float*)d_in[6];
    const float* Gamma      = (const float*)d_in[7];

    __half* qkv = nullptr;
    __half *sA = nullptr, *sB1 = nullptr, *sB2 = nullptr;
    cudaGetSymbolAddress((void**)&qkv, g_qkv);
    cudaGetSymbolAddress((void**)&sA, g_sA);
    cudaGetSymbolAddress((void**)&sB1, g_sB1);
    cudaGetSymbolAddress((void**)&sB2, g_sB2);

    static bool attr_set = false;
    if (!attr_set) {
        cudaFuncSetAttribute(gemm_mma, cudaFuncAttributeMaxDynamicSharedMemorySize, GEMM_SMEM);
        cudaFuncSetAttribute(stp_phaseA, cudaFuncAttributeMaxDynamicSharedMemorySize, PHA_SMEM);
        cudaFuncSetAttribute(stp_phaseB, cudaFuncAttributeMaxDynamicSharedMemorySize, PHB_SMEM);
        attr_set = true;
    }

    const long nx = (long)MTOT * ND;
    const long nw1 = (long)3 * ND * ND;
    const long nw2 = (long)ND * ND;

    // convert x, Wqkv_w to fp16
    cvt16_kernel<<<(unsigned)((nx / 8 + 255) / 256), 256>>>(x, sA, nx);
    cvt16_kernel<<<(unsigned)((nw1 / 8 + 255) / 256), 256>>>(Wqkv_w, sB1, nw1);
    // qkv (fp16) = x @ Wqkv_w^T + b
    gemm_mma<<<dim3(3 * ND / 128, MTOT / 128), 256, GEMM_SMEM>>>(
        sA, sB1, Wqkv_b, qkv, 3 * ND, ND, 1);

    // segmented scan: phase A -> combine -> phase B (writes y fp16 into sA)
    stp_phaseA<<<dim3(NB * NH, NSUBA), 512, PHA_SMEM>>>(Lambda_raw, Gamma);
    stp_combine<<<1024, 256>>>(Lambda_raw);
    stp_phaseB<<<dim3(NB * NH, 8), 512, PHB_SMEM>>>(W_static, Lambda_raw, Gamma);

    // convert out_w to fp16; out = y @ out_w^T + b (f32)
    cvt16_kernel<<<(unsigned)((nw2 / 8 + 255) / 256), 256>>>(out_w, sB2, nw2);
    gemm_mma<<<dim3(ND / 128, MTOT / 128), 256, GEMM_SMEM>>>(
        sA, sB2, out_b, d_out, ND, ND, 0);
}